// round 13
// baseline (speedup 1.0000x reference)
#include <cuda_runtime.h>
#include <math.h>

// ---------------- problem constants ----------------
#define Bn   16
#define NP   1296
#define DIM  768
#define Cc   201
#define Kp   5
#define DA   64
#define Nn   (Bn*NP)          // 20736
#define CK   (Cc*Kp)          // 1005

// output layout
#define OFF_CLASS  ((size_t)0)
#define LEN_CLASS  ((size_t)Bn*(Cc-1))
#define OFF_L      (OFF_CLASS + LEN_CLASS)
#define LEN_L      ((size_t)Nn*CK)
#define OFF_IMG    (OFF_L + LEN_L)
#define LEN_IMG    ((size_t)Bn*CK)
#define OFF_PART   (OFF_IMG + LEN_IMG)
#define LEN_PART   ((size_t)Nn)
#define OFF_PSEUDO (OFF_PART + LEN_PART)
#define LEN_PSEUDO ((size_t)Nn)
#define OFF_PNEW   (OFF_PSEUDO + LEN_PSEUDO)

#define FMA2(d,a,b,c) asm("fma.rn.f32x2 %0, %1, %2, %3;" : "=l"(d) : "l"(a), "l"(b), "l"(c))
#define PACK2(d,lo,hi) asm("mov.b64 %0, {%1, %2};" : "=l"(d) : "r"(__float_as_uint(lo)), "r"(__float_as_uint(hi)))

// ---------------- scratch ----------------
__device__ float g_proto_ad[CK*DA];
__device__ float g_feat_ad[(size_t)Nn*DA];
__device__ float g_invn[Nn];
__device__ int   g_labels_flat[Nn];
__device__ int   g_fgc[Bn];
__device__ int   g_rows[Nn];
__device__ int   g_pos[Nn];
__device__ float g_Lc[(size_t)Nn*Kp];
__device__ float g_Qc[(size_t)Nn*Kp];
__device__ float g_Ppart[(size_t)Bn*4*2*Kp*DIM];

// ---------------- zero img (atomicMax target; L > 0 strictly) ----------------
__global__ void zero_img(float* img) {
    int i = blockIdx.x*256 + threadIdx.x;
    if (i < Bn*CK) img[i] = 0.f;
}

// ---------------- proto_ad via tiled GEMM + fused sigmoid + shfl row-norm ----------
__global__ __launch_bounds__(256) void proto_gemm(const float* __restrict__ A,
                                                  const float* __restrict__ W,
                                                  const float* __restrict__ bias) {
    __shared__ __align__(16) unsigned long long As2[48*64];
    __shared__ float Bs[64][68];
    float* As2f = (float*)As2;
    int m0 = blockIdx.x*96;
    int t = threadIdx.x;
    int tx = t & 15, ty = t >> 4;
    unsigned long long acc2[3][4];
    #pragma unroll
    for (int i = 0; i < 3; i++)
        #pragma unroll
        for (int j = 0; j < 4; j++) acc2[i][j] = 0ull;

    for (int kc = 0; kc < DIM; kc += 64) {
        __syncthreads();
        #pragma unroll
        for (int i = 0; i < 24; i++) {
            int e = i*256 + t;
            int m = e >> 6, kk = e & 63;
            int rr = m0 + m; if (rr > CK-1) rr = CK-1;
            float v = A[(size_t)rr*DIM + kc + kk];
            As2f[(m >> 1)*128 + kk*2 + (m & 1)] = v;
        }
        #pragma unroll
        for (int i = 0; i < 16; i++) {
            int e = i*256 + t;
            int kk = e >> 6, c = e & 63;
            Bs[kk][c] = W[(size_t)(kc+kk)*DA + c];
        }
        __syncthreads();
        #pragma unroll
        for (int k4 = 0; k4 < 16; k4++) {
            int kk = k4*4;
            unsigned long long b2[4][4];
            #pragma unroll
            for (int jk = 0; jk < 4; jk++) {
                float4 bv = *(const float4*)&Bs[kk+jk][tx*4];
                PACK2(b2[jk][0], bv.x, bv.x);
                PACK2(b2[jk][1], bv.y, bv.y);
                PACK2(b2[jk][2], bv.z, bv.z);
                PACK2(b2[jk][3], bv.w, bv.w);
            }
            #pragma unroll
            for (int mp = 0; mp < 3; mp++) {
                const unsigned long long* arow = &As2[(ty*3+mp)*64 + kk];
                ulonglong2 a01 = *(const ulonglong2*)(arow);
                ulonglong2 a23 = *(const ulonglong2*)(arow + 2);
                #pragma unroll
                for (int j = 0; j < 4; j++) {
                    FMA2(acc2[mp][j], a01.x, b2[0][j], acc2[mp][j]);
                    FMA2(acc2[mp][j], a01.y, b2[1][j], acc2[mp][j]);
                    FMA2(acc2[mp][j], a23.x, b2[2][j], acc2[mp][j]);
                    FMA2(acc2[mp][j], a23.y, b2[3][j], acc2[mp][j]);
                }
            }
        }
    }
    float4 bv = *(const float4*)&bias[tx*4];
    float bb[4] = {bv.x, bv.y, bv.z, bv.w};
    #pragma unroll
    for (int mp = 0; mp < 3; mp++) {
        float lop[4], hip[4];
        #pragma unroll
        for (int j = 0; j < 4; j++) {
            float2 f = *(float2*)&acc2[mp][j];
            lop[j] = 1.f/(1.f + expf(-(f.x + bb[j])));
            hip[j] = 1.f/(1.f + expf(-(f.y + bb[j])));
        }
        float slo = lop[0]*lop[0] + lop[1]*lop[1] + lop[2]*lop[2] + lop[3]*lop[3];
        float shi = hip[0]*hip[0] + hip[1]*hip[1] + hip[2]*hip[2] + hip[3]*hip[3];
        #pragma unroll
        for (int o = 1; o < 16; o <<= 1) {
            slo += __shfl_xor_sync(0xffffffffu, slo, o);
            shi += __shfl_xor_sync(0xffffffffu, shi, o);
        }
        float dlo = 1.0f/fmaxf(sqrtf(slo), 1e-12f);
        float dhi = 1.0f/fmaxf(sqrtf(shi), 1e-12f);
        int m = m0 + ty*6 + mp*2;
        if (m < CK) {
            float4 o4; float* op = (float*)&o4;
            #pragma unroll
            for (int j = 0; j < 4; j++) op[j] = lop[j]*dlo;
            *(float4*)&g_proto_ad[(size_t)m*DA + tx*4] = o4;
        }
        if (m+1 < CK) {
            float4 o4; float* op = (float*)&o4;
            #pragma unroll
            for (int j = 0; j < 4; j++) op[j] = hip[j]*dhi;
            *(float4*)&g_proto_ad[(size_t)(m+1)*DA + tx*4] = o4;
        }
    }
}

// ---------------- inv L2 norm of each patch ----------------
__global__ __launch_bounds__(256) void norm_kernel(const float* __restrict__ patches) {
    int w = (blockIdx.x*256 + threadIdx.x) >> 5;
    int lane = threadIdx.x & 31;
    if (w >= Nn) return;
    const float4* p = (const float4*)(patches + (size_t)w*DIM);
    float s = 0.f;
    #pragma unroll
    for (int j = 0; j < 6; j++) {
        float4 v = p[lane + 32*j];
        s += v.x*v.x + v.y*v.y + v.z*v.z + v.w*v.w;
    }
    #pragma unroll
    for (int o = 16; o > 0; o >>= 1) s += __shfl_xor_sync(0xffffffffu, s, o);
    if (lane == 0) g_invn[w] = 1.0f/fmaxf(sqrtf(s), 1e-12f);
}

// ---------------- feat_ad = sigmoid(patch_tokens @ wf + bf)  (96x64, R9 config) -----
__global__ __launch_bounds__(256) void feat_gemm(const float* __restrict__ A,
                                                 const float* __restrict__ W,
                                                 const float* __restrict__ bias) {
    __shared__ __align__(16) unsigned long long As2[48*64];
    __shared__ float Bs[64][68];
    float* As2f = (float*)As2;
    int m0 = blockIdx.x*96;
    int t = threadIdx.x;
    int tx = t & 15, ty = t >> 4;
    unsigned long long acc2[3][4];
    #pragma unroll
    for (int i = 0; i < 3; i++)
        #pragma unroll
        for (int j = 0; j < 4; j++) acc2[i][j] = 0ull;

    for (int kc = 0; kc < DIM; kc += 64) {
        __syncthreads();
        #pragma unroll
        for (int i = 0; i < 24; i++) {
            int e = i*256 + t;
            int m = e >> 6, kk = e & 63;
            float v = A[(size_t)(m0+m)*DIM + kc + kk];
            As2f[(m >> 1)*128 + kk*2 + (m & 1)] = v;
        }
        #pragma unroll
        for (int i = 0; i < 16; i++) {
            int e = i*256 + t;
            int kk = e >> 6, c = e & 63;
            Bs[kk][c] = W[(size_t)(kc+kk)*DA + c];
        }
        __syncthreads();
        #pragma unroll
        for (int k4 = 0; k4 < 16; k4++) {
            int kk = k4*4;
            unsigned long long b2[4][4];
            #pragma unroll
            for (int jk = 0; jk < 4; jk++) {
                float4 bv = *(const float4*)&Bs[kk+jk][tx*4];
                PACK2(b2[jk][0], bv.x, bv.x);
                PACK2(b2[jk][1], bv.y, bv.y);
                PACK2(b2[jk][2], bv.z, bv.z);
                PACK2(b2[jk][3], bv.w, bv.w);
            }
            #pragma unroll
            for (int mp = 0; mp < 3; mp++) {
                const unsigned long long* arow = &As2[(ty*3+mp)*64 + kk];
                ulonglong2 a01 = *(const ulonglong2*)(arow);
                ulonglong2 a23 = *(const ulonglong2*)(arow + 2);
                #pragma unroll
                for (int j = 0; j < 4; j++) {
                    FMA2(acc2[mp][j], a01.x, b2[0][j], acc2[mp][j]);
                    FMA2(acc2[mp][j], a01.y, b2[1][j], acc2[mp][j]);
                    FMA2(acc2[mp][j], a23.x, b2[2][j], acc2[mp][j]);
                    FMA2(acc2[mp][j], a23.y, b2[3][j], acc2[mp][j]);
                }
            }
        }
    }
    float4 bv = *(const float4*)&bias[tx*4];
    float bb[4] = {bv.x, bv.y, bv.z, bv.w};
    #pragma unroll
    for (int mp = 0; mp < 3; mp++) {
        float4 lo4, hi4;
        float* lop = (float*)&lo4; float* hip = (float*)&hi4;
        #pragma unroll
        for (int j = 0; j < 4; j++) {
            float2 f = *(float2*)&acc2[mp][j];
            lop[j] = 1.f/(1.f + expf(-(f.x + bb[j])));
            hip[j] = 1.f/(1.f + expf(-(f.y + bb[j])));
        }
        int m = m0 + ty*6 + mp*2;
        *(float4*)&g_feat_ad[(size_t)m*DA + tx*4]     = lo4;
        *(float4*)&g_feat_ad[(size_t)(m+1)*DA + tx*4] = hi4;
    }
}

// ---------------- L = feat_ad @ proto_ad^T  + fused image-max epilogue ----------------
__global__ __launch_bounds__(256) void l_gemm(float* __restrict__ Lout,
                                              float* __restrict__ img) {
    __shared__ __align__(16) unsigned long long As2[48*64];
    __shared__ float Bs[64][68];
    float* As2f = (float*)As2;
    int m0 = blockIdx.x*96, n0 = blockIdx.y*64;
    int t = threadIdx.x, tx = t & 15, ty = t >> 4;
    #pragma unroll
    for (int i = 0; i < 24; i++) {
        int e = i*256 + t;
        int m = e >> 6, kk = e & 63;
        float v = g_feat_ad[(size_t)(m0+m)*DA + kk];
        As2f[(m >> 1)*128 + kk*2 + (m & 1)] = v;
    }
    #pragma unroll
    for (int i = 0; i < 16; i++) {
        int e = i*256 + t;
        int n = e >> 6, kk = e & 63;
        Bs[kk][n] = (n0+n < CK) ? g_proto_ad[(size_t)(n0+n)*DA + kk] : 0.f;
    }
    __syncthreads();
    unsigned long long acc2[3][4];
    #pragma unroll
    for (int i = 0; i < 3; i++)
        #pragma unroll
        for (int j = 0; j < 4; j++) acc2[i][j] = 0ull;
    #pragma unroll
    for (int k4 = 0; k4 < 16; k4++) {
        int kk = k4*4;
        unsigned long long b2[4][4];
        #pragma unroll
        for (int jk = 0; jk < 4; jk++) {
            float4 bv = *(const float4*)&Bs[kk+jk][tx*4];
            PACK2(b2[jk][0], bv.x, bv.x);
            PACK2(b2[jk][1], bv.y, bv.y);
            PACK2(b2[jk][2], bv.z, bv.z);
            PACK2(b2[jk][3], bv.w, bv.w);
        }
        #pragma unroll
        for (int mp = 0; mp < 3; mp++) {
            const unsigned long long* arow = &As2[(ty*3+mp)*64 + kk];
            ulonglong2 a01 = *(const ulonglong2*)(arow);
            ulonglong2 a23 = *(const ulonglong2*)(arow + 2);
            #pragma unroll
            for (int j = 0; j < 4; j++) {
                FMA2(acc2[mp][j], a01.x, b2[0][j], acc2[mp][j]);
                FMA2(acc2[mp][j], a01.y, b2[1][j], acc2[mp][j]);
                FMA2(acc2[mp][j], a23.x, b2[2][j], acc2[mp][j]);
                FMA2(acc2[mp][j], a23.y, b2[3][j], acc2[mp][j]);
            }
        }
    }
    // store L
    #pragma unroll
    for (int mp = 0; mp < 3; mp++) {
        size_t m = (size_t)(m0 + ty*6 + mp*2);
        #pragma unroll
        for (int j = 0; j < 4; j++) {
            int n = n0 + tx*4 + j;
            float2 f = *(float2*)&acc2[mp][j];
            if (n < CK) {
                Lout[m*CK + n]     = f.x;
                Lout[(m+1)*CK + n] = f.y;
            }
        }
    }
    // ---- fused image-max epilogue (reuse Bs as reduce buffer) ----
    int imgF = m0 / NP;
    int imgL = (m0 + 95) / NP;
    float tm[2][4];
    #pragma unroll
    for (int p = 0; p < 2; p++)
        #pragma unroll
        for (int j = 0; j < 4; j++) tm[p][j] = 0.f;
    #pragma unroll
    for (int mp = 0; mp < 3; mp++) {
        int r0 = ty*6 + mp*2;
        int g0 = (m0 + r0)/NP - imgF;        // 0 or 1
        int g1 = (m0 + r0 + 1)/NP - imgF;
        #pragma unroll
        for (int j = 0; j < 4; j++) {
            float2 f = *(float2*)&acc2[mp][j];
            tm[g0][j] = fmaxf(tm[g0][j], f.x);
            tm[g1][j] = fmaxf(tm[g1][j], f.y);
        }
    }
    __syncthreads();   // mainloop reads of Bs complete before reuse
    float* red = &Bs[0][0];  // treat as [32][68]
    #pragma unroll
    for (int p = 0; p < 2; p++)
        #pragma unroll
        for (int j = 0; j < 4; j++)
            red[(p*16 + ty)*68 + tx*4 + j] = tm[p][j];
    __syncthreads();
    #pragma unroll
    for (int off = 8; off > 0; off >>= 1) {
        if (ty < off) {
            #pragma unroll
            for (int p = 0; p < 2; p++)
                #pragma unroll
                for (int j = 0; j < 4; j++) {
                    int idx = (p*16 + ty)*68 + tx*4 + j;
                    red[idx] = fmaxf(red[idx], red[idx + off*68]);
                }
        }
        __syncthreads();
    }
    if (ty == 0) {
        #pragma unroll
        for (int j = 0; j < 4; j++) {
            int n = n0 + tx*4 + j;
            if (n < CK) {
                atomicMax((int*)&img[(size_t)imgF*CK + n], __float_as_int(red[tx*4 + j]));
                if (imgL != imgF)
                    atomicMax((int*)&img[(size_t)imgL*CK + n], __float_as_int(red[16*68 + tx*4 + j]));
            }
        }
    }
}

// ---------------- class_logits (img is complete) ----------------
__global__ __launch_bounds__(1024) void classlog_kernel(const float* __restrict__ img,
                                                        const float* __restrict__ sa,
                                                        float* __restrict__ cls) {
    __shared__ float s_img[CK];
    int b = blockIdx.x, ck = threadIdx.x;
    if (ck < CK) s_img[ck] = img[(size_t)b*CK + ck];
    __syncthreads();
    int c = ck;
    if (c < Cc-1) {
        float s[Kp]; float mx = -INFINITY;
        #pragma unroll
        for (int k = 0; k < Kp; k++) { s[k] = sa[c*Kp + k]; mx = fmaxf(mx, s[k]); }
        float e[Kp]; float tot = 0.f;
        #pragma unroll
        for (int k = 0; k < Kp; k++) { e[k] = expf(s[k]-mx); tot += e[k]; }
        float acc = 0.f;
        #pragma unroll
        for (int k = 0; k < Kp; k++) acc += s_img[c*Kp + k]*(e[k]/tot*(float)Kp);
        cls[(size_t)b*(Cc-1) + c] = acc;
    }
}

// ---------------- pseudo labels + per-image fg counts ----------------
__global__ __launch_bounds__(512) void pseudo_kernel(const float* __restrict__ L,
                                                     const int* __restrict__ labels,
                                                     float* __restrict__ out_pl) {
    __shared__ float fg[NP], bg[NP];
    __shared__ float red[512];
    __shared__ int ired[512];
    int b = blockIdx.x, t = threadIdx.x;
    int lab = labels[b];
    for (int n = t; n < NP; n += 512) {
        const float* p = L + ((size_t)b*NP + n)*CK;
        float f = 0.f, g = 0.f;
        #pragma unroll
        for (int k = 0; k < Kp; k++) { f += p[lab*Kp + k]; g += p[(Cc-1)*Kp + k]; }
        fg[n] = f; bg[n] = g;
    }
    __syncthreads();
    float sf = 0.f, sb = 0.f;
    for (int n = t; n < NP; n += 512) { sf += fabsf(fg[n]); sb += fabsf(bg[n]); }
    red[t] = sf; __syncthreads();
    for (int off = 256; off > 0; off >>= 1) { if (t < off) red[t] += red[t+off]; __syncthreads(); }
    float Sf = fmaxf(red[0], 1e-12f); __syncthreads();
    red[t] = sb; __syncthreads();
    for (int off = 256; off > 0; off >>= 1) { if (t < off) red[t] += red[t+off]; __syncthreads(); }
    float Sb = fmaxf(red[0], 1e-12f); __syncthreads();
    int fgc = 0;
    for (int n = t; n < NP; n += 512) {
        bool m = (fg[n]/Sf) > (bg[n]/Sb);
        int pl = m ? lab : (Cc-1);
        out_pl[(size_t)b*NP + n] = (float)pl;
        g_labels_flat[b*NP + n] = pl;
        fgc += m ? 1 : 0;
    }
    ired[t] = fgc; __syncthreads();
    for (int off = 256; off > 0; off >>= 1) { if (t < off) ired[t] += ired[t+off]; __syncthreads(); }
    if (t == 0) g_fgc[b] = ired[0];
}

// ---------------- compact rows + gather own-class L into g_Lc ----------------
__global__ __launch_bounds__(512) void compact_kernel(const int* __restrict__ labels,
                                                      const float* __restrict__ L) {
    __shared__ int scan[512];
    __shared__ int s_fgc[Bn], s_lab[Bn];
    int b = blockIdx.x, t = threadIdx.x;
    if (t < Bn) { s_fgc[t] = g_fgc[t]; s_lab[t] = labels[t]; }
    __syncthreads();
    int lab = s_lab[b];
    int fg_base = 0, bg_base = 0, total_fg = 0;
    #pragma unroll
    for (int i = 0; i < Bn; i++) {
        total_fg += s_fgc[i];
        if (s_lab[i] < lab || (s_lab[i] == lab && i < b)) fg_base += s_fgc[i];
        if (i < b) bg_base += NP - s_fgc[i];
    }
    int c0 = t*3;
    int m[3]; int cnt = 0;
    #pragma unroll
    for (int j = 0; j < 3; j++) {
        int n = c0 + j;
        int f = 0;
        if (n < NP) f = (g_labels_flat[b*NP + n] != Cc-1) ? 1 : 0;
        m[j] = f; cnt += f;
    }
    scan[t] = cnt;
    __syncthreads();
    for (int off = 1; off < 512; off <<= 1) {
        int v = (t >= off) ? scan[t-off] : 0;
        __syncthreads();
        scan[t] += v;
        __syncthreads();
    }
    int fgr = scan[t] - cnt;
    #pragma unroll
    for (int j = 0; j < 3; j++) {
        int n = c0 + j;
        if (n < NP) {
            int gn = b*NP + n;
            int idx, cc;
            if (m[j]) { idx = fg_base + fgr; fgr++; cc = lab; }
            else      { idx = total_fg + bg_base + (n - fgr); cc = Cc-1; }
            g_rows[idx] = gn;
            g_pos[gn]   = idx;
            const float* ps = L + (size_t)gn*CK + cc*Kp;
            float* lc = g_Lc + (size_t)idx*Kp;
            #pragma unroll
            for (int k = 0; k < Kp; k++) lc[k] = ps[k];
        }
    }
}

// ---------------- masked sinkhorn on fully compacted arrays ----------------
__global__ __launch_bounds__(512) void sinkhorn_kernel(const int* __restrict__ labels,
                                                       float* __restrict__ out_part) {
    int c = blockIdx.x, t = threadIdx.x;
    int start = 0, cnt = 0, total_fg = 0;
    #pragma unroll
    for (int i = 0; i < Bn; i++) {
        int f = g_fgc[i]; int li = labels[i];
        total_fg += f;
        if (c < Cc-1) {
            if (li < c) start += f;
            if (li == c) cnt += f;
        }
    }
    if (c == Cc-1) { start = total_fg; cnt = Nn - total_fg; }
    if (cnt == 0) return;
    int end = start + cnt;

    __shared__ float wred[16][6];
    __shared__ float bc[6];
    int lane = t & 31, wid = t >> 5;

    float lm = -INFINITY;
    for (int i = start + t; i < end; i += 512) {
        const float* p = g_Lc + (size_t)i*Kp;
        #pragma unroll
        for (int k = 0; k < Kp; k++) lm = fmaxf(lm, p[k]);
    }
    #pragma unroll
    for (int o = 16; o > 0; o >>= 1) lm = fmaxf(lm, __shfl_xor_sync(0xffffffffu, lm, o));
    if (lane == 0) wred[wid][0] = lm;
    __syncthreads();
    if (wid == 0) {
        float v = (lane < 16) ? wred[lane][0] : -INFINITY;
        #pragma unroll
        for (int o = 8; o > 0; o >>= 1) v = fmaxf(v, __shfl_xor_sync(0xffffffffu, v, o));
        if (lane == 0) bc[0] = v;
    }
    __syncthreads();
    float lmax = bc[0];
    __syncthreads();

    float cs[Kp] = {0,0,0,0,0};
    float tot = 0.f;
    for (int i = start + t; i < end; i += 512) {
        const float* p = g_Lc + (size_t)i*Kp;
        float* q = g_Qc + (size_t)i*Kp;
        #pragma unroll
        for (int k = 0; k < Kp; k++) {
            float e = expf((p[k]-lmax)/0.05f);
            q[k] = e; cs[k] += e; tot += e;
        }
    }
    {
        float v[6] = {cs[0], cs[1], cs[2], cs[3], cs[4], tot};
        #pragma unroll
        for (int j = 0; j < 6; j++)
            #pragma unroll
            for (int o = 16; o > 0; o >>= 1) v[j] += __shfl_xor_sync(0xffffffffu, v[j], o);
        if (lane == 0)
            #pragma unroll
            for (int j = 0; j < 6; j++) wred[wid][j] = v[j];
        __syncthreads();
        if (wid == 0) {
            float w[6];
            #pragma unroll
            for (int j = 0; j < 6; j++) w[j] = (lane < 16) ? wred[lane][j] : 0.f;
            #pragma unroll
            for (int j = 0; j < 6; j++)
                #pragma unroll
                for (int o = 8; o > 0; o >>= 1) w[j] += __shfl_xor_sync(0xffffffffu, w[j], o);
            if (lane == 0)
                #pragma unroll
                for (int j = 0; j < 6; j++) bc[j] = w[j];
        }
        __syncthreads();
    }
    float Ttot = fmaxf(bc[5], 1e-12f);
    float a[Kp];
    #pragma unroll
    for (int k = 0; k < Kp; k++) {
        float mk = fmaxf(bc[k]/Ttot, 1e-12f);
        a[k] = 1.0f/(Ttot*mk*5.0f);
    }
    __syncthreads();
    float ncinv = 1.0f/fmaxf((float)cnt, 1.0f);

    for (int it = 0; it < 3; it++) {
        float ncs[Kp] = {0,0,0,0,0};
        for (int i = start + t; i < end; i += 512) {
            float* q = g_Qc + (size_t)i*Kp;
            float w[Kp]; float rs = 0.f;
            #pragma unroll
            for (int k = 0; k < Kp; k++) { w[k] = q[k]*a[k]; rs += w[k]; }
            float rinv = 1.0f/fmaxf(rs, 1e-12f);
            if (it < 2) {
                #pragma unroll
                for (int k = 0; k < Kp; k++) {
                    float v = w[k]*rinv*ncinv;
                    q[k] = v; ncs[k] += v;
                }
            } else {
                int bi = 0; float best = -1.f;
                #pragma unroll
                for (int k = 0; k < Kp; k++) {
                    float v = w[k]*rinv;
                    q[k] = v;
                    if (v > best) { best = v; bi = k; }
                }
                out_part[g_rows[i]] = (float)(bi + c*Kp);
            }
        }
        if (it < 2) {
            #pragma unroll
            for (int j = 0; j < Kp; j++)
                #pragma unroll
                for (int o = 16; o > 0; o >>= 1) ncs[j] += __shfl_xor_sync(0xffffffffu, ncs[j], o);
            if (lane == 0)
                #pragma unroll
                for (int j = 0; j < Kp; j++) wred[wid][j] = ncs[j];
            __syncthreads();
            if (wid == 0) {
                float w[Kp];
                #pragma unroll
                for (int j = 0; j < Kp; j++) w[j] = (lane < 16) ? wred[lane][j] : 0.f;
                #pragma unroll
                for (int j = 0; j < Kp; j++)
                    #pragma unroll
                    for (int o = 8; o > 0; o >>= 1) w[j] += __shfl_xor_sync(0xffffffffu, w[j], o);
                if (lane == 0)
                    #pragma unroll
                    for (int j = 0; j < Kp; j++) bc[j] = w[j];
            }
            __syncthreads();
            #pragma unroll
            for (int k = 0; k < Kp; k++)
                a[k] = 1.0f/(fmaxf(bc[k], 1e-12f)*5.0f);
            __syncthreads();
        }
    }
}

// ---------------- P_cand partials ----------------
__global__ __launch_bounds__(128) void pcand_part(const float* __restrict__ patches) {
    int b = blockIdx.x, dc = blockIdx.y, ps = blockIdx.z, t = threadIdx.x;
    float accF[Kp] = {0,0,0,0,0};
    float accB[Kp] = {0,0,0,0,0};
    int n0 = b*NP + ps*324;
    const float* base = patches + (size_t)dc*128 + t;
    #pragma unroll 8
    for (int p = 0; p < 324; p++) {
        int n = n0 + p;
        float v = base[(size_t)n*DIM] * g_invn[n];
        int lab = g_labels_flat[n];
        const float* q = g_Qc + (size_t)g_pos[n]*Kp;
        if (lab == Cc-1) {
            #pragma unroll
            for (int k = 0; k < Kp; k++) accB[k] += q[k]*v;
        } else {
            #pragma unroll
            for (int k = 0; k < Kp; k++) accF[k] += q[k]*v;
        }
    }
    int d = dc*128 + t;
    size_t baseF = ((((size_t)b*4 + ps)*2 + 0)*Kp)*DIM + d;
    size_t baseB = ((((size_t)b*4 + ps)*2 + 1)*Kp)*DIM + d;
    #pragma unroll
    for (int k = 0; k < Kp; k++) {
        g_Ppart[baseF + (size_t)k*DIM] = accF[k];
        g_Ppart[baseB + (size_t)k*DIM] = accB[k];
    }
}

// ---------------- P_new ----------------
__global__ __launch_bounds__(256) void pnew_kernel(const float* __restrict__ proto,
                                                   const int* __restrict__ labels,
                                                   float* __restrict__ out) {
    __shared__ int s_lab[Bn], s_fg[Bn];
    int ck = blockIdx.x, t = threadIdx.x;
    int c = ck/Kp, k = ck - c*Kp;
    if (t < Bn) { s_lab[t] = labels[t]; s_fg[t] = g_fgc[t]; }
    __syncthreads();
    bool isbg = (c == Cc-1);
    bool present;
    if (isbg) {
        int tf = 0;
        #pragma unroll
        for (int b = 0; b < Bn; b++) tf += s_fg[b];
        present = (Nn - tf) > 0;
    } else {
        present = false;
        #pragma unroll
        for (int b = 0; b < Bn; b++)
            if (s_lab[b] == c && s_fg[b] > 0) present = true;
    }
    for (int d = t; d < DIM; d += 256) {
        size_t idx = (size_t)ck*DIM + d;
        float p = proto[idx];
        float r = p;
        if (present) {
            float s = 0.f;
            if (isbg) {
                #pragma unroll
                for (int b = 0; b < Bn; b++)
                    #pragma unroll
                    for (int ps = 0; ps < 4; ps++)
                        s += g_Ppart[((((size_t)b*4 + ps)*2 + 1)*Kp + k)*DIM + d];
            } else {
                for (int b = 0; b < Bn; b++) {
                    if (s_lab[b] == c) {
                        #pragma unroll
                        for (int ps = 0; ps < 4; ps++)
                            s += g_Ppart[((((size_t)b*4 + ps)*2 + 0)*Kp + k)*DIM + d];
                    }
                }
            }
            r = 0.999f*p + 0.001f*s;
        }
        out[idx] = r;
    }
}

// ---------------- launch ----------------
extern "C" void kernel_launch(void* const* d_in, const int* in_sizes, int n_in,
                              void* d_out, int out_size) {
    const float* patch  = (const float*)d_in[0];
    const float* proto  = (const float*)d_in[1];
    const float* sa     = (const float*)d_in[2];
    const float* wf     = (const float*)d_in[3];
    const float* bf     = (const float*)d_in[4];
    const float* wp     = (const float*)d_in[5];
    const float* bp     = (const float*)d_in[6];
    const int*   labels = (const int*)d_in[7];
    float* out  = (float*)d_out;
    float* Lout = out + OFF_L;
    float* img  = out + OFF_IMG;

    zero_img<<<(Bn*CK + 255)/256, 256>>>(img);                    // 0
    proto_gemm<<<(CK+95)/96, 256>>>(proto, wp, bp);               // 1
    feat_gemm<<<Nn/96, 256>>>(patch, wf, bf);                     // 2
    l_gemm<<<dim3(Nn/96, (CK+63)/64), 256>>>(Lout, img);          // 3  <- capture slot
    pseudo_kernel<<<Bn, 512>>>(Lout, labels, out + OFF_PSEUDO);   // 4
    norm_kernel<<<(Nn*32)/256, 256>>>(patch);                     // 5
    classlog_kernel<<<Bn, 1024>>>(img, sa, out + OFF_CLASS);      // 6
    compact_kernel<<<Bn, 512>>>(labels, Lout);                    // 7
    sinkhorn_kernel<<<Cc, 512>>>(labels, out + OFF_PART);         // 8
    pcand_part<<<dim3(Bn, 6, 4), 128>>>(patch);                   // 9
    pnew_kernel<<<CK, 256>>>(proto, labels, out + OFF_PNEW);      // 10
}

// round 14
// speedup vs baseline: 1.0434x; 1.0434x over previous
#include <cuda_runtime.h>
#include <math.h>

// ---------------- problem constants ----------------
#define Bn   16
#define NP   1296
#define DIM  768
#define Cc   201
#define Kp   5
#define DA   64
#define Nn   (Bn*NP)          // 20736
#define CK   (Cc*Kp)          // 1005

// output layout
#define OFF_CLASS  ((size_t)0)
#define LEN_CLASS  ((size_t)Bn*(Cc-1))
#define OFF_L      (OFF_CLASS + LEN_CLASS)
#define LEN_L      ((size_t)Nn*CK)
#define OFF_IMG    (OFF_L + LEN_L)
#define LEN_IMG    ((size_t)Bn*CK)
#define OFF_PART   (OFF_IMG + LEN_IMG)
#define LEN_PART   ((size_t)Nn)
#define OFF_PSEUDO (OFF_PART + LEN_PART)
#define LEN_PSEUDO ((size_t)Nn)
#define OFF_PNEW   (OFF_PSEUDO + LEN_PSEUDO)

#define FMA2(d,a,b,c) asm("fma.rn.f32x2 %0, %1, %2, %3;" : "=l"(d) : "l"(a), "l"(b), "l"(c))
#define PACK2(d,lo,hi) asm("mov.b64 %0, {%1, %2};" : "=l"(d) : "r"(__float_as_uint(lo)), "r"(__float_as_uint(hi)))

#define NBLK 64   // max sinkhorn plan blocks (bound: 17 + Nn/512 ~ 58)

// ---------------- scratch ----------------
__device__ float g_proto_ad[CK*DA];
__device__ float g_feat_ad[(size_t)Nn*DA];
__device__ float g_invn[Nn];
__device__ int   g_labels_flat[Nn];
__device__ int   g_fgc[Bn];
__device__ int   g_rows[Nn];
__device__ int   g_pos[Nn];
__device__ float g_Lc[(size_t)Nn*Kp];
__device__ float g_Qc[(size_t)Nn*Kp];
__device__ float g_imgpart[(size_t)Bn*16*CK];
__device__ float g_Ppart[(size_t)Bn*4*2*Kp*DIM];
// sinkhorn plan + partials
__device__ int   g_plan_cls[NBLK];
__device__ int   g_plan_row[NBLK];
__device__ int   g_plan_end[NBLK];
__device__ int   g_nplan;
__device__ int   g_cstart[256], g_ccnt[256], g_cfb[256];
__device__ float g_bmax[NBLK];
__device__ float g_bcs[NBLK*Kp];
__device__ float g_lmax[256];
__device__ float g_a[256*Kp];
__device__ float g_ncinv[256];

// ---------------- proto_ad (per-row, 425.8 config) ----------------
__global__ __launch_bounds__(64) void proto_kernel(const float* __restrict__ proto,
                                                   const float* __restrict__ wp,
                                                   const float* __restrict__ bp) {
    __shared__ float4 rowv[DIM/4];
    __shared__ float red[64];
    int r = blockIdx.x;
    int t = threadIdx.x;
    const float4* src = (const float4*)(proto + (size_t)r*DIM);
    #pragma unroll
    for (int j = 0; j < 3; j++) rowv[t + 64*j] = src[t + 64*j];
    __syncthreads();
    float s0 = bp[t], s1 = 0.f, s2 = 0.f, s3 = 0.f;
    #pragma unroll 4
    for (int d4 = 0; d4 < DIM/4; d4++) {
        float4 rv = rowv[d4];
        int d = d4*4;
        s0 += rv.x*wp[(size_t)d*DA + t];
        s1 += rv.y*wp[(size_t)(d+1)*DA + t];
        s2 += rv.z*wp[(size_t)(d+2)*DA + t];
        s3 += rv.w*wp[(size_t)(d+3)*DA + t];
    }
    float v = 1.f/(1.f + expf(-((s0+s1)+(s2+s3))));
    red[t] = v*v;
    __syncthreads();
    for (int off = 32; off > 0; off >>= 1) {
        if (t < off) red[t] += red[t+off];
        __syncthreads();
    }
    float denom = fmaxf(sqrtf(red[0]), 1e-12f);
    g_proto_ad[(size_t)r*DA + t] = v/denom;
}

// ---------------- inv L2 norm of each patch ----------------
__global__ __launch_bounds__(256) void norm_kernel(const float* __restrict__ patches) {
    int w = (blockIdx.x*256 + threadIdx.x) >> 5;
    int lane = threadIdx.x & 31;
    if (w >= Nn) return;
    const float4* p = (const float4*)(patches + (size_t)w*DIM);
    float s = 0.f;
    #pragma unroll
    for (int j = 0; j < 6; j++) {
        float4 v = p[lane + 32*j];
        s += v.x*v.x + v.y*v.y + v.z*v.z + v.w*v.w;
    }
    #pragma unroll
    for (int o = 16; o > 0; o >>= 1) s += __shfl_xor_sync(0xffffffffu, s, o);
    if (lane == 0) g_invn[w] = 1.0f/fmaxf(sqrtf(s), 1e-12f);
}

// ---------------- feat_ad (96x64, 425.8 config) ----------------
__global__ __launch_bounds__(256) void feat_gemm(const float* __restrict__ A,
                                                 const float* __restrict__ W,
                                                 const float* __restrict__ bias) {
    __shared__ __align__(16) unsigned long long As2[48*64];
    __shared__ float Bs[64][68];
    float* As2f = (float*)As2;
    int m0 = blockIdx.x*96;
    int t = threadIdx.x;
    int tx = t & 15, ty = t >> 4;
    unsigned long long acc2[3][4];
    #pragma unroll
    for (int i = 0; i < 3; i++)
        #pragma unroll
        for (int j = 0; j < 4; j++) acc2[i][j] = 0ull;

    for (int kc = 0; kc < DIM; kc += 64) {
        __syncthreads();
        #pragma unroll
        for (int i = 0; i < 24; i++) {
            int e = i*256 + t;
            int m = e >> 6, kk = e & 63;
            float v = A[(size_t)(m0+m)*DIM + kc + kk];
            As2f[(m >> 1)*128 + kk*2 + (m & 1)] = v;
        }
        #pragma unroll
        for (int i = 0; i < 16; i++) {
            int e = i*256 + t;
            int kk = e >> 6, c = e & 63;
            Bs[kk][c] = W[(size_t)(kc+kk)*DA + c];
        }
        __syncthreads();
        #pragma unroll
        for (int k4 = 0; k4 < 16; k4++) {
            int kk = k4*4;
            unsigned long long b2[4][4];
            #pragma unroll
            for (int jk = 0; jk < 4; jk++) {
                float4 bv = *(const float4*)&Bs[kk+jk][tx*4];
                PACK2(b2[jk][0], bv.x, bv.x);
                PACK2(b2[jk][1], bv.y, bv.y);
                PACK2(b2[jk][2], bv.z, bv.z);
                PACK2(b2[jk][3], bv.w, bv.w);
            }
            #pragma unroll
            for (int mp = 0; mp < 3; mp++) {
                const unsigned long long* arow = &As2[(ty*3+mp)*64 + kk];
                ulonglong2 a01 = *(const ulonglong2*)(arow);
                ulonglong2 a23 = *(const ulonglong2*)(arow + 2);
                #pragma unroll
                for (int j = 0; j < 4; j++) {
                    FMA2(acc2[mp][j], a01.x, b2[0][j], acc2[mp][j]);
                    FMA2(acc2[mp][j], a01.y, b2[1][j], acc2[mp][j]);
                    FMA2(acc2[mp][j], a23.x, b2[2][j], acc2[mp][j]);
                    FMA2(acc2[mp][j], a23.y, b2[3][j], acc2[mp][j]);
                }
            }
        }
    }
    float4 bv = *(const float4*)&bias[tx*4];
    float bb[4] = {bv.x, bv.y, bv.z, bv.w};
    #pragma unroll
    for (int mp = 0; mp < 3; mp++) {
        float4 lo4, hi4;
        float* lop = (float*)&lo4; float* hip = (float*)&hi4;
        #pragma unroll
        for (int j = 0; j < 4; j++) {
            float2 f = *(float2*)&acc2[mp][j];
            lop[j] = 1.f/(1.f + expf(-(f.x + bb[j])));
            hip[j] = 1.f/(1.f + expf(-(f.y + bb[j])));
        }
        int m = m0 + ty*6 + mp*2;
        *(float4*)&g_feat_ad[(size_t)m*DA + tx*4]     = lo4;
        *(float4*)&g_feat_ad[(size_t)(m+1)*DA + tx*4] = hi4;
    }
}

// ---------------- L = feat_ad @ proto_ad^T  (96x64, 425.8 config) ----------------
__global__ __launch_bounds__(256) void l_gemm(float* __restrict__ Lout) {
    __shared__ __align__(16) unsigned long long As2[48*64];
    __shared__ float Bs[64][68];
    float* As2f = (float*)As2;
    int m0 = blockIdx.x*96, n0 = blockIdx.y*64;
    int t = threadIdx.x, tx = t & 15, ty = t >> 4;
    #pragma unroll
    for (int i = 0; i < 24; i++) {
        int e = i*256 + t;
        int m = e >> 6, kk = e & 63;
        float v = g_feat_ad[(size_t)(m0+m)*DA + kk];
        As2f[(m >> 1)*128 + kk*2 + (m & 1)] = v;
    }
    #pragma unroll
    for (int i = 0; i < 16; i++) {
        int e = i*256 + t;
        int n = e >> 6, kk = e & 63;
        Bs[kk][n] = (n0+n < CK) ? g_proto_ad[(size_t)(n0+n)*DA + kk] : 0.f;
    }
    __syncthreads();
    unsigned long long acc2[3][4];
    #pragma unroll
    for (int i = 0; i < 3; i++)
        #pragma unroll
        for (int j = 0; j < 4; j++) acc2[i][j] = 0ull;
    #pragma unroll
    for (int k4 = 0; k4 < 16; k4++) {
        int kk = k4*4;
        unsigned long long b2[4][4];
        #pragma unroll
        for (int jk = 0; jk < 4; jk++) {
            float4 bv = *(const float4*)&Bs[kk+jk][tx*4];
            PACK2(b2[jk][0], bv.x, bv.x);
            PACK2(b2[jk][1], bv.y, bv.y);
            PACK2(b2[jk][2], bv.z, bv.z);
            PACK2(b2[jk][3], bv.w, bv.w);
        }
        #pragma unroll
        for (int mp = 0; mp < 3; mp++) {
            const unsigned long long* arow = &As2[(ty*3+mp)*64 + kk];
            ulonglong2 a01 = *(const ulonglong2*)(arow);
            ulonglong2 a23 = *(const ulonglong2*)(arow + 2);
            #pragma unroll
            for (int j = 0; j < 4; j++) {
                FMA2(acc2[mp][j], a01.x, b2[0][j], acc2[mp][j]);
                FMA2(acc2[mp][j], a01.y, b2[1][j], acc2[mp][j]);
                FMA2(acc2[mp][j], a23.x, b2[2][j], acc2[mp][j]);
                FMA2(acc2[mp][j], a23.y, b2[3][j], acc2[mp][j]);
            }
        }
    }
    #pragma unroll
    for (int mp = 0; mp < 3; mp++) {
        size_t m = (size_t)(m0 + ty*6 + mp*2);
        #pragma unroll
        for (int j = 0; j < 4; j++) {
            int n = n0 + tx*4 + j;
            float2 f = *(float2*)&acc2[mp][j];
            if (n < CK) {
                Lout[m*CK + n]     = f.x;
                Lout[(m+1)*CK + n] = f.y;
            }
        }
    }
}

// ---------------- image_logits stage 1 ----------------
__global__ __launch_bounds__(1024) void imgmax_part(const float* __restrict__ L) {
    int b = blockIdx.x;
    int j = blockIdx.y;
    int ck = threadIdx.x;
    if (ck >= CK) return;
    const float* base = L + ((size_t)b*NP + (size_t)j*81)*CK + ck;
    float m = 0.f;
    #pragma unroll 3
    for (int n = 0; n < 81; n++) m = fmaxf(m, base[(size_t)n*CK]);
    g_imgpart[((size_t)b*16 + j)*CK + ck] = m;
}

// ---------------- image_logits stage 2 + class_logits ----------------
__global__ __launch_bounds__(1024) void imgmax_reduce(float* __restrict__ img,
                                                      const float* __restrict__ sa,
                                                      float* __restrict__ cls) {
    __shared__ float s_img[CK];
    int b = blockIdx.x, ck = threadIdx.x;
    if (ck < CK) {
        float m = 0.f;
        #pragma unroll
        for (int j = 0; j < 16; j++)
            m = fmaxf(m, g_imgpart[((size_t)b*16 + j)*CK + ck]);
        img[(size_t)b*CK + ck] = m;
        s_img[ck] = m;
    }
    __syncthreads();
    int c = ck;
    if (c < Cc-1) {
        float s[Kp]; float mx = -INFINITY;
        #pragma unroll
        for (int k = 0; k < Kp; k++) { s[k] = sa[c*Kp + k]; mx = fmaxf(mx, s[k]); }
        float e[Kp]; float tot = 0.f;
        #pragma unroll
        for (int k = 0; k < Kp; k++) { e[k] = expf(s[k]-mx); tot += e[k]; }
        float acc = 0.f;
        #pragma unroll
        for (int k = 0; k < Kp; k++) acc += s_img[c*Kp + k]*(e[k]/tot*(float)Kp);
        cls[(size_t)b*(Cc-1) + c] = acc;
    }
}

// ---------------- pseudo labels + per-image fg counts ----------------
__global__ __launch_bounds__(512) void pseudo_kernel(const float* __restrict__ L,
                                                     const int* __restrict__ labels,
                                                     float* __restrict__ out_pl) {
    __shared__ float fg[NP], bg[NP];
    __shared__ float red[512];
    __shared__ int ired[512];
    int b = blockIdx.x, t = threadIdx.x;
    int lab = labels[b];
    for (int n = t; n < NP; n += 512) {
        const float* p = L + ((size_t)b*NP + n)*CK;
        float f = 0.f, g = 0.f;
        #pragma unroll
        for (int k = 0; k < Kp; k++) { f += p[lab*Kp + k]; g += p[(Cc-1)*Kp + k]; }
        fg[n] = f; bg[n] = g;
    }
    __syncthreads();
    float sf = 0.f, sb = 0.f;
    for (int n = t; n < NP; n += 512) { sf += fabsf(fg[n]); sb += fabsf(bg[n]); }
    red[t] = sf; __syncthreads();
    for (int off = 256; off > 0; off >>= 1) { if (t < off) red[t] += red[t+off]; __syncthreads(); }
    float Sf = fmaxf(red[0], 1e-12f); __syncthreads();
    red[t] = sb; __syncthreads();
    for (int off = 256; off > 0; off >>= 1) { if (t < off) red[t] += red[t+off]; __syncthreads(); }
    float Sb = fmaxf(red[0], 1e-12f); __syncthreads();
    int fgc = 0;
    for (int n = t; n < NP; n += 512) {
        bool m = (fg[n]/Sf) > (bg[n]/Sb);
        int pl = m ? lab : (Cc-1);
        out_pl[(size_t)b*NP + n] = (float)pl;
        g_labels_flat[b*NP + n] = pl;
        fgc += m ? 1 : 0;
    }
    ired[t] = fgc; __syncthreads();
    for (int off = 256; off > 0; off >>= 1) { if (t < off) ired[t] += ired[t+off]; __syncthreads(); }
    if (t == 0) g_fgc[b] = ired[0];
}

// ---------------- compact rows + gather own-class L into g_Lc ----------------
__global__ __launch_bounds__(512) void compact_kernel(const int* __restrict__ labels,
                                                      const float* __restrict__ L) {
    __shared__ int scan[512];
    __shared__ int s_fgc[Bn], s_lab[Bn];
    int b = blockIdx.x, t = threadIdx.x;
    if (t < Bn) { s_fgc[t] = g_fgc[t]; s_lab[t] = labels[t]; }
    __syncthreads();
    int lab = s_lab[b];
    int fg_base = 0, bg_base = 0, total_fg = 0;
    #pragma unroll
    for (int i = 0; i < Bn; i++) {
        total_fg += s_fgc[i];
        if (s_lab[i] < lab || (s_lab[i] == lab && i < b)) fg_base += s_fgc[i];
        if (i < b) bg_base += NP - s_fgc[i];
    }
    int c0 = t*3;
    int m[3]; int cnt = 0;
    #pragma unroll
    for (int j = 0; j < 3; j++) {
        int n = c0 + j;
        int f = 0;
        if (n < NP) f = (g_labels_flat[b*NP + n] != Cc-1) ? 1 : 0;
        m[j] = f; cnt += f;
    }
    scan[t] = cnt;
    __syncthreads();
    for (int off = 1; off < 512; off <<= 1) {
        int v = (t >= off) ? scan[t-off] : 0;
        __syncthreads();
        scan[t] += v;
        __syncthreads();
    }
    int fgr = scan[t] - cnt;
    #pragma unroll
    for (int j = 0; j < 3; j++) {
        int n = c0 + j;
        if (n < NP) {
            int gn = b*NP + n;
            int idx, cc;
            if (m[j]) { idx = fg_base + fgr; fgr++; cc = lab; }
            else      { idx = total_fg + bg_base + (n - fgr); cc = Cc-1; }
            g_rows[idx] = gn;
            g_pos[gn]   = idx;
            const float* ps = L + (size_t)gn*CK + cc*Kp;
            float* lc = g_Lc + (size_t)idx*Kp;
            #pragma unroll
            for (int k = 0; k < Kp; k++) lc[k] = ps[k];
        }
    }
}

// ---------------- sinkhorn plan: block-aligned class segments ----------------
__global__ __launch_bounds__(256) void plan_kernel(const int* __restrict__ labels) {
    __shared__ int s_fgc[Bn], s_lab[Bn];
    __shared__ int s_nb[256];
    int t = threadIdx.x;
    if (t < Bn) { s_fgc[t] = g_fgc[t]; s_lab[t] = labels[t]; }
    __syncthreads();
    int start = 0, cnt = 0, nb = 0;
    if (t < Cc) {
        if (t < Cc-1) {
            #pragma unroll
            for (int i = 0; i < Bn; i++) {
                if (s_lab[i] < t) start += s_fgc[i];
                if (s_lab[i] == t) cnt += s_fgc[i];
            }
        } else {
            int tf = 0;
            #pragma unroll
            for (int i = 0; i < Bn; i++) tf += s_fgc[i];
            start = tf; cnt = Nn - tf;
        }
        nb = (cnt + 511)/512;
    }
    s_nb[t] = nb;
    __syncthreads();
    for (int off = 1; off < 256; off <<= 1) {
        int v = (t >= off) ? s_nb[t-off] : 0;
        __syncthreads();
        s_nb[t] += v;
        __syncthreads();
    }
    int fb = s_nb[t] - nb;
    if (t < Cc) {
        g_cstart[t] = start; g_ccnt[t] = cnt; g_cfb[t] = fb;
        for (int j = 0; j < nb; j++) {
            g_plan_cls[fb+j] = t;
            g_plan_row[fb+j] = start + j*512;
            int e = start + j*512 + 512;
            g_plan_end[fb+j] = (e < start+cnt) ? e : (start+cnt);
        }
    }
    if (t == 255) g_nplan = s_nb[255];
}

// ---------------- sinkhorn phase kernels ----------------
__global__ __launch_bounds__(512) void sh_lmax_part() {
    int b = blockIdx.x;
    if (b >= g_nplan) return;
    int t = threadIdx.x, lane = t & 31, wid = t >> 5;
    __shared__ float wred[16];
    int r = g_plan_row[b] + t;
    float m = -INFINITY;
    if (r < g_plan_end[b]) {
        const float* p = g_Lc + (size_t)r*Kp;
        #pragma unroll
        for (int k = 0; k < Kp; k++) m = fmaxf(m, p[k]);
    }
    #pragma unroll
    for (int o = 16; o > 0; o >>= 1) m = fmaxf(m, __shfl_xor_sync(0xffffffffu, m, o));
    if (lane == 0) wred[wid] = m;
    __syncthreads();
    if (wid == 0) {
        float v = (lane < 16) ? wred[lane] : -INFINITY;
        #pragma unroll
        for (int o = 8; o > 0; o >>= 1) v = fmaxf(v, __shfl_xor_sync(0xffffffffu, v, o));
        if (lane == 0) g_bmax[b] = v;
    }
}

__global__ __launch_bounds__(32) void sh_lmax_red() {
    int c = blockIdx.x;
    int cnt = g_ccnt[c];
    if (cnt == 0 || threadIdx.x != 0) return;
    int fb = g_cfb[c], nb = (cnt + 511)/512;
    float m = -INFINITY;
    for (int j = 0; j < nb; j++) m = fmaxf(m, g_bmax[fb+j]);
    g_lmax[c] = m;
    g_ncinv[c] = 1.0f/fmaxf((float)cnt, 1.0f);
}

__global__ __launch_bounds__(512) void sh_exp_part() {
    int b = blockIdx.x;
    if (b >= g_nplan) return;
    int t = threadIdx.x, lane = t & 31, wid = t >> 5;
    __shared__ float wred[16][Kp];
    int c = g_plan_cls[b];
    float lmax = g_lmax[c];
    int r = g_plan_row[b] + t;
    float v[Kp] = {0,0,0,0,0};
    if (r < g_plan_end[b]) {
        const float* p = g_Lc + (size_t)r*Kp;
        float* q = g_Qc + (size_t)r*Kp;
        #pragma unroll
        for (int k = 0; k < Kp; k++) {
            float e = expf((p[k]-lmax)/0.05f);
            q[k] = e; v[k] = e;
        }
    }
    #pragma unroll
    for (int j = 0; j < Kp; j++)
        #pragma unroll
        for (int o = 16; o > 0; o >>= 1) v[j] += __shfl_xor_sync(0xffffffffu, v[j], o);
    if (lane == 0)
        #pragma unroll
        for (int j = 0; j < Kp; j++) wred[wid][j] = v[j];
    __syncthreads();
    if (wid == 0) {
        float w[Kp];
        #pragma unroll
        for (int j = 0; j < Kp; j++) w[j] = (lane < 16) ? wred[lane][j] : 0.f;
        #pragma unroll
        for (int j = 0; j < Kp; j++)
            #pragma unroll
            for (int o = 8; o > 0; o >>= 1) w[j] += __shfl_xor_sync(0xffffffffu, w[j], o);
        if (lane == 0)
            #pragma unroll
            for (int j = 0; j < Kp; j++) g_bcs[b*Kp + j] = w[j];
    }
}

__global__ __launch_bounds__(32) void sh_exp_red() {
    int c = blockIdx.x;
    int cnt = g_ccnt[c];
    if (cnt == 0 || threadIdx.x != 0) return;
    int fb = g_cfb[c], nb = (cnt + 511)/512;
    float cs[Kp] = {0,0,0,0,0};
    for (int j = 0; j < nb; j++)
        #pragma unroll
        for (int k = 0; k < Kp; k++) cs[k] += g_bcs[(fb+j)*Kp + k];
    float Ttot = fmaxf(cs[0]+cs[1]+cs[2]+cs[3]+cs[4], 1e-12f);
    #pragma unroll
    for (int k = 0; k < Kp; k++) {
        float mk = fmaxf(cs[k]/Ttot, 1e-12f);
        g_a[c*Kp + k] = 1.0f/(Ttot*mk*5.0f);
    }
}

template<bool LAST>
__global__ __launch_bounds__(512) void sh_it_part(float* __restrict__ out_part) {
    int b = blockIdx.x;
    if (b >= g_nplan) return;
    int t = threadIdx.x, lane = t & 31, wid = t >> 5;
    __shared__ float wred[16][Kp];
    int c = g_plan_cls[b];
    float a[Kp];
    #pragma unroll
    for (int k = 0; k < Kp; k++) a[k] = g_a[c*Kp + k];
    float ncinv = g_ncinv[c];
    int r = g_plan_row[b] + t;
    float v[Kp] = {0,0,0,0,0};
    if (r < g_plan_end[b]) {
        float* q = g_Qc + (size_t)r*Kp;
        float w[Kp]; float rs = 0.f;
        #pragma unroll
        for (int k = 0; k < Kp; k++) { w[k] = q[k]*a[k]; rs += w[k]; }
        float rinv = 1.0f/fmaxf(rs, 1e-12f);
        if (!LAST) {
            #pragma unroll
            for (int k = 0; k < Kp; k++) {
                float vv = w[k]*rinv*ncinv;
                q[k] = vv; v[k] = vv;
            }
        } else {
            int bi = 0; float best = -1.f;
            #pragma unroll
            for (int k = 0; k < Kp; k++) {
                float vv = w[k]*rinv;
                q[k] = vv;
                if (vv > best) { best = vv; bi = k; }
            }
            out_part[g_rows[r]] = (float)(bi + c*Kp);
        }
    }
    if (!LAST) {
        #pragma unroll
        for (int j = 0; j < Kp; j++)
            #pragma unroll
            for (int o = 16; o > 0; o >>= 1) v[j] += __shfl_xor_sync(0xffffffffu, v[j], o);
        if (lane == 0)
            #pragma unroll
            for (int j = 0; j < Kp; j++) wred[wid][j] = v[j];
        __syncthreads();
        if (wid == 0) {
            float w[Kp];
            #pragma unroll
            for (int j = 0; j < Kp; j++) w[j] = (lane < 16) ? wred[lane][j] : 0.f;
            #pragma unroll
            for (int j = 0; j < Kp; j++)
                #pragma unroll
                for (int o = 8; o > 0; o >>= 1) w[j] += __shfl_xor_sync(0xffffffffu, w[j], o);
            if (lane == 0)
                #pragma unroll
                for (int j = 0; j < Kp; j++) g_bcs[b*Kp + j] = w[j];
        }
    }
}

__global__ __launch_bounds__(32) void sh_it_red() {
    int c = blockIdx.x;
    int cnt = g_ccnt[c];
    if (cnt == 0 || threadIdx.x != 0) return;
    int fb = g_cfb[c], nb = (cnt + 511)/512;
    float cs[Kp] = {0,0,0,0,0};
    for (int j = 0; j < nb; j++)
        #pragma unroll
        for (int k = 0; k < Kp; k++) cs[k] += g_bcs[(fb+j)*Kp + k];
    #pragma unroll
    for (int k = 0; k < Kp; k++)
        g_a[c*Kp + k] = 1.0f/(fmaxf(cs[k], 1e-12f)*5.0f);
}

// ---------------- P_cand partials ----------------
__global__ __launch_bounds__(128) void pcand_part(const float* __restrict__ patches) {
    int b = blockIdx.x, dc = blockIdx.y, ps = blockIdx.z, t = threadIdx.x;
    float accF[Kp] = {0,0,0,0,0};
    float accB[Kp] = {0,0,0,0,0};
    int n0 = b*NP + ps*324;
    const float* base = patches + (size_t)dc*128 + t;
    #pragma unroll 8
    for (int p = 0; p < 324; p++) {
        int n = n0 + p;
        float v = base[(size_t)n*DIM] * g_invn[n];
        int lab = g_labels_flat[n];
        const float* q = g_Qc + (size_t)g_pos[n]*Kp;
        if (lab == Cc-1) {
            #pragma unroll
            for (int k = 0; k < Kp; k++) accB[k] += q[k]*v;
        } else {
            #pragma unroll
            for (int k = 0; k < Kp; k++) accF[k] += q[k]*v;
        }
    }
    int d = dc*128 + t;
    size_t baseF = ((((size_t)b*4 + ps)*2 + 0)*Kp)*DIM + d;
    size_t baseB = ((((size_t)b*4 + ps)*2 + 1)*Kp)*DIM + d;
    #pragma unroll
    for (int k = 0; k < Kp; k++) {
        g_Ppart[baseF + (size_t)k*DIM] = accF[k];
        g_Ppart[baseB + (size_t)k*DIM] = accB[k];
    }
}

// ---------------- P_new ----------------
__global__ __launch_bounds__(256) void pnew_kernel(const float* __restrict__ proto,
                                                   const int* __restrict__ labels,
                                                   float* __restrict__ out) {
    __shared__ int s_lab[Bn], s_fg[Bn];
    int ck = blockIdx.x, t = threadIdx.x;
    int c = ck/Kp, k = ck - c*Kp;
    if (t < Bn) { s_lab[t] = labels[t]; s_fg[t] = g_fgc[t]; }
    __syncthreads();
    bool isbg = (c == Cc-1);
    bool present;
    if (isbg) {
        int tf = 0;
        #pragma unroll
        for (int b = 0; b < Bn; b++) tf += s_fg[b];
        present = (Nn - tf) > 0;
    } else {
        present = false;
        #pragma unroll
        for (int b = 0; b < Bn; b++)
            if (s_lab[b] == c && s_fg[b] > 0) present = true;
    }
    for (int d = t; d < DIM; d += 256) {
        size_t idx = (size_t)ck*DIM + d;
        float p = proto[idx];
        float r = p;
        if (present) {
            float s = 0.f;
            if (isbg) {
                #pragma unroll
                for (int b = 0; b < Bn; b++)
                    #pragma unroll
                    for (int ps = 0; ps < 4; ps++)
                        s += g_Ppart[((((size_t)b*4 + ps)*2 + 1)*Kp + k)*DIM + d];
            } else {
                for (int b = 0; b < Bn; b++) {
                    if (s_lab[b] == c) {
                        #pragma unroll
                        for (int ps = 0; ps < 4; ps++)
                            s += g_Ppart[((((size_t)b*4 + ps)*2 + 0)*Kp + k)*DIM + d];
                    }
                }
            }
            r = 0.999f*p + 0.001f*s;
        }
        out[idx] = r;
    }
}

// ---------------- launch ----------------
extern "C" void kernel_launch(void* const* d_in, const int* in_sizes, int n_in,
                              void* d_out, int out_size) {
    const float* patch  = (const float*)d_in[0];
    const float* proto  = (const float*)d_in[1];
    const float* sa     = (const float*)d_in[2];
    const float* wf     = (const float*)d_in[3];
    const float* bf     = (const float*)d_in[4];
    const float* wp     = (const float*)d_in[5];
    const float* bp     = (const float*)d_in[6];
    const int*   labels = (const int*)d_in[7];
    float* out  = (float*)d_out;
    float* Lout = out + OFF_L;
    float* img  = out + OFF_IMG;

    proto_kernel<<<CK, 64>>>(proto, wp, bp);                      // 0
    feat_gemm<<<Nn/96, 256>>>(patch, wf, bf);                     // 1
    norm_kernel<<<(Nn*32)/256, 256>>>(patch);                     // 2
    l_gemm<<<dim3(Nn/96, (CK+63)/64), 256>>>(Lout);               // 3  <- capture slot (control)
    imgmax_part<<<dim3(Bn, 16), 1024>>>(Lout);                    // 4
    imgmax_reduce<<<Bn, 1024>>>(img, sa, out + OFF_CLASS);        // 5
    pseudo_kernel<<<Bn, 512>>>(Lout, labels, out + OFF_PSEUDO);   // 6
    compact_kernel<<<Bn, 512>>>(labels, Lout);                    // 7
    plan_kernel<<<1, 256>>>(labels);                              // 8
    sh_lmax_part<<<NBLK, 512>>>();                                // 9
    sh_lmax_red<<<Cc, 32>>>();                                    // 10
    sh_exp_part<<<NBLK, 512>>>();                                 // 11
    sh_exp_red<<<Cc, 32>>>();                                     // 12
    sh_it_part<false><<<NBLK, 512>>>(out + OFF_PART);             // 13
    sh_it_red<<<Cc, 32>>>();                                      // 14
    sh_it_part<false><<<NBLK, 512>>>(out + OFF_PART);             // 15
    sh_it_red<<<Cc, 32>>>();                                      // 16
    sh_it_part<true><<<NBLK, 512>>>(out + OFF_PART);              // 17
    pcand_part<<<dim3(Bn, 6, 4), 128>>>(patch);                   // 18
    pnew_kernel<<<CK, 256>>>(proto, labels, out + OFF_PNEW);      // 19
}

// round 15
// speedup vs baseline: 1.2409x; 1.1892x over previous
#include <cuda_runtime.h>
#include <math.h>

// ---------------- problem constants ----------------
#define Bn   16
#define NP   1296
#define DIM  768
#define Cc   201
#define Kp   5
#define DA   64
#define Nn   (Bn*NP)          // 20736
#define CK   (Cc*Kp)          // 1005

// output layout
#define OFF_CLASS  ((size_t)0)
#define LEN_CLASS  ((size_t)Bn*(Cc-1))
#define OFF_L      (OFF_CLASS + LEN_CLASS)
#define LEN_L      ((size_t)Nn*CK)
#define OFF_IMG    (OFF_L + LEN_L)
#define LEN_IMG    ((size_t)Bn*CK)
#define OFF_PART   (OFF_IMG + LEN_IMG)
#define LEN_PART   ((size_t)Nn)
#define OFF_PSEUDO (OFF_PART + LEN_PART)
#define LEN_PSEUDO ((size_t)Nn)
#define OFF_PNEW   (OFF_PSEUDO + LEN_PSEUDO)

#define FMA2(d,a,b,c) asm("fma.rn.f32x2 %0, %1, %2, %3;" : "=l"(d) : "l"(a), "l"(b), "l"(c))
#define PACK2(d,lo,hi) asm("mov.b64 %0, {%1, %2};" : "=l"(d) : "r"(__float_as_uint(lo)), "r"(__float_as_uint(hi)))

#define NBLK 64
#define PS   8     // pcand patch-splits per image

// ---------------- scratch ----------------
__device__ float g_proto_ad[CK*DA];
__device__ float g_feat_ad[(size_t)Nn*DA];
__device__ float g_invn[Nn];
__device__ int   g_labels_flat[Nn];
__device__ int   g_fgc[Bn];
__device__ int   g_rows[Nn];
__device__ int   g_pos[Nn];
__device__ float g_Lc[(size_t)Nn*Kp];
__device__ float g_Qc[(size_t)Nn*Kp];
__device__ float g_imgpart[(size_t)Bn*16*CK];
__device__ float g_Ppart[(size_t)Bn*PS*2*Kp*DIM];
// sinkhorn plan + partials
__device__ int   g_plan_cls[NBLK];
__device__ int   g_plan_row[NBLK];
__device__ int   g_plan_end[NBLK];
__device__ int   g_nplan;
__device__ int   g_cstart[256], g_ccnt[256], g_cfb[256];
__device__ float g_bmax[NBLK];
__device__ float g_bcs[NBLK*Kp];
__device__ float g_lmax[256];
__device__ float g_a[256*Kp];
__device__ float g_ncinv[256];

// ---------------- inv L2 norm of each patch (half range per launch) ----------------
__global__ __launch_bounds__(256) void norm_kernel(const float* __restrict__ patches, int base) {
    int w = base + ((blockIdx.x*256 + threadIdx.x) >> 5);
    int lane = threadIdx.x & 31;
    if (w >= Nn) return;
    const float4* p = (const float4*)(patches + (size_t)w*DIM);
    float s = 0.f;
    #pragma unroll
    for (int j = 0; j < 6; j++) {
        float4 v = p[lane + 32*j];
        s += v.x*v.x + v.y*v.y + v.z*v.z + v.w*v.w;
    }
    #pragma unroll
    for (int o = 16; o > 0; o >>= 1) s += __shfl_xor_sync(0xffffffffu, s, o);
    if (lane == 0) g_invn[w] = 1.0f/fmaxf(sqrtf(s), 1e-12f);
}

// ---------------- proto_ad via tiled GEMM + fused sigmoid + shfl row-norm ----------
__global__ __launch_bounds__(256) void proto_gemm(const float* __restrict__ A,
                                                  const float* __restrict__ W,
                                                  const float* __restrict__ bias) {
    __shared__ __align__(16) unsigned long long As2[48*64];
    __shared__ float Bs[64][68];
    float* As2f = (float*)As2;
    int m0 = blockIdx.x*96;
    int t = threadIdx.x;
    int tx = t & 15, ty = t >> 4;
    unsigned long long acc2[3][4];
    #pragma unroll
    for (int i = 0; i < 3; i++)
        #pragma unroll
        for (int j = 0; j < 4; j++) acc2[i][j] = 0ull;

    for (int kc = 0; kc < DIM; kc += 64) {
        __syncthreads();
        #pragma unroll
        for (int i = 0; i < 24; i++) {
            int e = i*256 + t;
            int m = e >> 6, kk = e & 63;
            int rr = m0 + m; if (rr > CK-1) rr = CK-1;
            float v = A[(size_t)rr*DIM + kc + kk];
            As2f[(m >> 1)*128 + kk*2 + (m & 1)] = v;
        }
        #pragma unroll
        for (int i = 0; i < 16; i++) {
            int e = i*256 + t;
            int kk = e >> 6, c = e & 63;
            Bs[kk][c] = W[(size_t)(kc+kk)*DA + c];
        }
        __syncthreads();
        #pragma unroll
        for (int k4 = 0; k4 < 16; k4++) {
            int kk = k4*4;
            unsigned long long b2[4][4];
            #pragma unroll
            for (int jk = 0; jk < 4; jk++) {
                float4 bv = *(const float4*)&Bs[kk+jk][tx*4];
                PACK2(b2[jk][0], bv.x, bv.x);
                PACK2(b2[jk][1], bv.y, bv.y);
                PACK2(b2[jk][2], bv.z, bv.z);
                PACK2(b2[jk][3], bv.w, bv.w);
            }
            #pragma unroll
            for (int mp = 0; mp < 3; mp++) {
                const unsigned long long* arow = &As2[(ty*3+mp)*64 + kk];
                ulonglong2 a01 = *(const ulonglong2*)(arow);
                ulonglong2 a23 = *(const ulonglong2*)(arow + 2);
                #pragma unroll
                for (int j = 0; j < 4; j++) {
                    FMA2(acc2[mp][j], a01.x, b2[0][j], acc2[mp][j]);
                    FMA2(acc2[mp][j], a01.y, b2[1][j], acc2[mp][j]);
                    FMA2(acc2[mp][j], a23.x, b2[2][j], acc2[mp][j]);
                    FMA2(acc2[mp][j], a23.y, b2[3][j], acc2[mp][j]);
                }
            }
        }
    }
    float4 bv = *(const float4*)&bias[tx*4];
    float bb[4] = {bv.x, bv.y, bv.z, bv.w};
    #pragma unroll
    for (int mp = 0; mp < 3; mp++) {
        float lop[4], hip[4];
        #pragma unroll
        for (int j = 0; j < 4; j++) {
            float2 f = *(float2*)&acc2[mp][j];
            lop[j] = 1.f/(1.f + expf(-(f.x + bb[j])));
            hip[j] = 1.f/(1.f + expf(-(f.y + bb[j])));
        }
        float slo = lop[0]*lop[0] + lop[1]*lop[1] + lop[2]*lop[2] + lop[3]*lop[3];
        float shi = hip[0]*hip[0] + hip[1]*hip[1] + hip[2]*hip[2] + hip[3]*hip[3];
        #pragma unroll
        for (int o = 1; o < 16; o <<= 1) {
            slo += __shfl_xor_sync(0xffffffffu, slo, o);
            shi += __shfl_xor_sync(0xffffffffu, shi, o);
        }
        float dlo = 1.0f/fmaxf(sqrtf(slo), 1e-12f);
        float dhi = 1.0f/fmaxf(sqrtf(shi), 1e-12f);
        int m = m0 + ty*6 + mp*2;
        if (m < CK) {
            float4 o4; float* op = (float*)&o4;
            #pragma unroll
            for (int j = 0; j < 4; j++) op[j] = lop[j]*dlo;
            *(float4*)&g_proto_ad[(size_t)m*DA + tx*4] = o4;
        }
        if (m+1 < CK) {
            float4 o4; float* op = (float*)&o4;
            #pragma unroll
            for (int j = 0; j < 4; j++) op[j] = hip[j]*dhi;
            *(float4*)&g_proto_ad[(size_t)(m+1)*DA + tx*4] = o4;
        }
    }
}

// ---------------- feat_ad (96x64, 425.8 config) ----------------
__global__ __launch_bounds__(256) void feat_gemm(const float* __restrict__ A,
                                                 const float* __restrict__ W,
                                                 const float* __restrict__ bias) {
    __shared__ __align__(16) unsigned long long As2[48*64];
    __shared__ float Bs[64][68];
    float* As2f = (float*)As2;
    int m0 = blockIdx.x*96;
    int t = threadIdx.x;
    int tx = t & 15, ty = t >> 4;
    unsigned long long acc2[3][4];
    #pragma unroll
    for (int i = 0; i < 3; i++)
        #pragma unroll
        for (int j = 0; j < 4; j++) acc2[i][j] = 0ull;

    for (int kc = 0; kc < DIM; kc += 64) {
        __syncthreads();
        #pragma unroll
        for (int i = 0; i < 24; i++) {
            int e = i*256 + t;
            int m = e >> 6, kk = e & 63;
            float v = A[(size_t)(m0+m)*DIM + kc + kk];
            As2f[(m >> 1)*128 + kk*2 + (m & 1)] = v;
        }
        #pragma unroll
        for (int i = 0; i < 16; i++) {
            int e = i*256 + t;
            int kk = e >> 6, c = e & 63;
            Bs[kk][c] = W[(size_t)(kc+kk)*DA + c];
        }
        __syncthreads();
        #pragma unroll
        for (int k4 = 0; k4 < 16; k4++) {
            int kk = k4*4;
            unsigned long long b2[4][4];
            #pragma unroll
            for (int jk = 0; jk < 4; jk++) {
                float4 bv = *(const float4*)&Bs[kk+jk][tx*4];
                PACK2(b2[jk][0], bv.x, bv.x);
                PACK2(b2[jk][1], bv.y, bv.y);
                PACK2(b2[jk][2], bv.z, bv.z);
                PACK2(b2[jk][3], bv.w, bv.w);
            }
            #pragma unroll
            for (int mp = 0; mp < 3; mp++) {
                const unsigned long long* arow = &As2[(ty*3+mp)*64 + kk];
                ulonglong2 a01 = *(const ulonglong2*)(arow);
                ulonglong2 a23 = *(const ulonglong2*)(arow + 2);
                #pragma unroll
                for (int j = 0; j < 4; j++) {
                    FMA2(acc2[mp][j], a01.x, b2[0][j], acc2[mp][j]);
                    FMA2(acc2[mp][j], a01.y, b2[1][j], acc2[mp][j]);
                    FMA2(acc2[mp][j], a23.x, b2[2][j], acc2[mp][j]);
                    FMA2(acc2[mp][j], a23.y, b2[3][j], acc2[mp][j]);
                }
            }
        }
    }
    float4 bv = *(const float4*)&bias[tx*4];
    float bb[4] = {bv.x, bv.y, bv.z, bv.w};
    #pragma unroll
    for (int mp = 0; mp < 3; mp++) {
        float4 lo4, hi4;
        float* lop = (float*)&lo4; float* hip = (float*)&hi4;
        #pragma unroll
        for (int j = 0; j < 4; j++) {
            float2 f = *(float2*)&acc2[mp][j];
            lop[j] = 1.f/(1.f + expf(-(f.x + bb[j])));
            hip[j] = 1.f/(1.f + expf(-(f.y + bb[j])));
        }
        int m = m0 + ty*6 + mp*2;
        *(float4*)&g_feat_ad[(size_t)m*DA + tx*4]     = lo4;
        *(float4*)&g_feat_ad[(size_t)(m+1)*DA + tx*4] = hi4;
    }
}

// ---------------- L = feat_ad @ proto_ad^T  (96x64, 425.8 config) ----------------
__global__ __launch_bounds__(256) void l_gemm(float* __restrict__ Lout) {
    __shared__ __align__(16) unsigned long long As2[48*64];
    __shared__ float Bs[64][68];
    float* As2f = (float*)As2;
    int m0 = blockIdx.x*96, n0 = blockIdx.y*64;
    int t = threadIdx.x, tx = t & 15, ty = t >> 4;
    #pragma unroll
    for (int i = 0; i < 24; i++) {
        int e = i*256 + t;
        int m = e >> 6, kk = e & 63;
        float v = g_feat_ad[(size_t)(m0+m)*DA + kk];
        As2f[(m >> 1)*128 + kk*2 + (m & 1)] = v;
    }
    #pragma unroll
    for (int i = 0; i < 16; i++) {
        int e = i*256 + t;
        int n = e >> 6, kk = e & 63;
        Bs[kk][n] = (n0+n < CK) ? g_proto_ad[(size_t)(n0+n)*DA + kk] : 0.f;
    }
    __syncthreads();
    unsigned long long acc2[3][4];
    #pragma unroll
    for (int i = 0; i < 3; i++)
        #pragma unroll
        for (int j = 0; j < 4; j++) acc2[i][j] = 0ull;
    #pragma unroll
    for (int k4 = 0; k4 < 16; k4++) {
        int kk = k4*4;
        unsigned long long b2[4][4];
        #pragma unroll
        for (int jk = 0; jk < 4; jk++) {
            float4 bv = *(const float4*)&Bs[kk+jk][tx*4];
            PACK2(b2[jk][0], bv.x, bv.x);
            PACK2(b2[jk][1], bv.y, bv.y);
            PACK2(b2[jk][2], bv.z, bv.z);
            PACK2(b2[jk][3], bv.w, bv.w);
        }
        #pragma unroll
        for (int mp = 0; mp < 3; mp++) {
            const unsigned long long* arow = &As2[(ty*3+mp)*64 + kk];
            ulonglong2 a01 = *(const ulonglong2*)(arow);
            ulonglong2 a23 = *(const ulonglong2*)(arow + 2);
            #pragma unroll
            for (int j = 0; j < 4; j++) {
                FMA2(acc2[mp][j], a01.x, b2[0][j], acc2[mp][j]);
                FMA2(acc2[mp][j], a01.y, b2[1][j], acc2[mp][j]);
                FMA2(acc2[mp][j], a23.x, b2[2][j], acc2[mp][j]);
                FMA2(acc2[mp][j], a23.y, b2[3][j], acc2[mp][j]);
            }
        }
    }
    #pragma unroll
    for (int mp = 0; mp < 3; mp++) {
        size_t m = (size_t)(m0 + ty*6 + mp*2);
        #pragma unroll
        for (int j = 0; j < 4; j++) {
            int n = n0 + tx*4 + j;
            float2 f = *(float2*)&acc2[mp][j];
            if (n < CK) {
                Lout[m*CK + n]     = f.x;
                Lout[(m+1)*CK + n] = f.y;
            }
        }
    }
}

// ---------------- image_logits stage 1 (3 independent max chains) ----------------
__global__ __launch_bounds__(1024) void imgmax_part(const float* __restrict__ L) {
    int b = blockIdx.x;
    int j = blockIdx.y;
    int ck = threadIdx.x;
    if (ck >= CK) return;
    const float* base = L + ((size_t)b*NP + (size_t)j*81)*CK + ck;
    float m0 = 0.f, m1 = 0.f, m2 = 0.f;
    #pragma unroll 3
    for (int n = 0; n < 81; n += 3) {
        m0 = fmaxf(m0, base[(size_t)n*CK]);
        m1 = fmaxf(m1, base[(size_t)(n+1)*CK]);
        m2 = fmaxf(m2, base[(size_t)(n+2)*CK]);
    }
    g_imgpart[((size_t)b*16 + j)*CK + ck] = fmaxf(fmaxf(m0, m1), m2);
}

// ---------------- image_logits stage 2 + class_logits ----------------
__global__ __launch_bounds__(1024) void imgmax_reduce(float* __restrict__ img,
                                                      const float* __restrict__ sa,
                                                      float* __restrict__ cls) {
    __shared__ float s_img[CK];
    int b = blockIdx.x, ck = threadIdx.x;
    if (ck < CK) {
        float m = 0.f;
        #pragma unroll
        for (int j = 0; j < 16; j++)
            m = fmaxf(m, g_imgpart[((size_t)b*16 + j)*CK + ck]);
        img[(size_t)b*CK + ck] = m;
        s_img[ck] = m;
    }
    __syncthreads();
    int c = ck;
    if (c < Cc-1) {
        float s[Kp]; float mx = -INFINITY;
        #pragma unroll
        for (int k = 0; k < Kp; k++) { s[k] = sa[c*Kp + k]; mx = fmaxf(mx, s[k]); }
        float e[Kp]; float tot = 0.f;
        #pragma unroll
        for (int k = 0; k < Kp; k++) { e[k] = expf(s[k]-mx); tot += e[k]; }
        float acc = 0.f;
        #pragma unroll
        for (int k = 0; k < Kp; k++) acc += s_img[c*Kp + k]*(e[k]/tot*(float)Kp);
        cls[(size_t)b*(Cc-1) + c] = acc;
    }
}

// ---------------- pseudo labels + per-image fg counts ----------------
__global__ __launch_bounds__(512) void pseudo_kernel(const float* __restrict__ L,
                                                     const int* __restrict__ labels,
                                                     float* __restrict__ out_pl) {
    __shared__ float fg[NP], bg[NP];
    __shared__ float red[512];
    __shared__ int ired[512];
    int b = blockIdx.x, t = threadIdx.x;
    int lab = labels[b];
    for (int n = t; n < NP; n += 512) {
        const float* p = L + ((size_t)b*NP + n)*CK;
        float f = 0.f, g = 0.f;
        #pragma unroll
        for (int k = 0; k < Kp; k++) { f += p[lab*Kp + k]; g += p[(Cc-1)*Kp + k]; }
        fg[n] = f; bg[n] = g;
    }
    __syncthreads();
    float sf = 0.f, sb = 0.f;
    for (int n = t; n < NP; n += 512) { sf += fabsf(fg[n]); sb += fabsf(bg[n]); }
    red[t] = sf; __syncthreads();
    for (int off = 256; off > 0; off >>= 1) { if (t < off) red[t] += red[t+off]; __syncthreads(); }
    float Sf = fmaxf(red[0], 1e-12f); __syncthreads();
    red[t] = sb; __syncthreads();
    for (int off = 256; off > 0; off >>= 1) { if (t < off) red[t] += red[t+off]; __syncthreads(); }
    float Sb = fmaxf(red[0], 1e-12f); __syncthreads();
    int fgc = 0;
    for (int n = t; n < NP; n += 512) {
        bool m = (fg[n]/Sf) > (bg[n]/Sb);
        int pl = m ? lab : (Cc-1);
        out_pl[(size_t)b*NP + n] = (float)pl;
        g_labels_flat[b*NP + n] = pl;
        fgc += m ? 1 : 0;
    }
    ired[t] = fgc; __syncthreads();
    for (int off = 256; off > 0; off >>= 1) { if (t < off) ired[t] += ired[t+off]; __syncthreads(); }
    if (t == 0) g_fgc[b] = ired[0];
}

// ---------------- compact rows + gather own-class L into g_Lc ----------------
__global__ __launch_bounds__(512) void compact_kernel(const int* __restrict__ labels,
                                                      const float* __restrict__ L) {
    __shared__ int scan[512];
    __shared__ int s_fgc[Bn], s_lab[Bn];
    int b = blockIdx.x, t = threadIdx.x;
    if (t < Bn) { s_fgc[t] = g_fgc[t]; s_lab[t] = labels[t]; }
    __syncthreads();
    int lab = s_lab[b];
    int fg_base = 0, bg_base = 0, total_fg = 0;
    #pragma unroll
    for (int i = 0; i < Bn; i++) {
        total_fg += s_fgc[i];
        if (s_lab[i] < lab || (s_lab[i] == lab && i < b)) fg_base += s_fgc[i];
        if (i < b) bg_base += NP - s_fgc[i];
    }
    int c0 = t*3;
    int m[3]; int cnt = 0;
    #pragma unroll
    for (int j = 0; j < 3; j++) {
        int n = c0 + j;
        int f = 0;
        if (n < NP) f = (g_labels_flat[b*NP + n] != Cc-1) ? 1 : 0;
        m[j] = f; cnt += f;
    }
    scan[t] = cnt;
    __syncthreads();
    for (int off = 1; off < 512; off <<= 1) {
        int v = (t >= off) ? scan[t-off] : 0;
        __syncthreads();
        scan[t] += v;
        __syncthreads();
    }
    int fgr = scan[t] - cnt;
    #pragma unroll
    for (int j = 0; j < 3; j++) {
        int n = c0 + j;
        if (n < NP) {
            int gn = b*NP + n;
            int idx, cc;
            if (m[j]) { idx = fg_base + fgr; fgr++; cc = lab; }
            else      { idx = total_fg + bg_base + (n - fgr); cc = Cc-1; }
            g_rows[idx] = gn;
            g_pos[gn]   = idx;
            const float* ps = L + (size_t)gn*CK + cc*Kp;
            float* lc = g_Lc + (size_t)idx*Kp;
            #pragma unroll
            for (int k = 0; k < Kp; k++) lc[k] = ps[k];
        }
    }
}

// ---------------- sinkhorn plan ----------------
__global__ __launch_bounds__(256) void plan_kernel(const int* __restrict__ labels) {
    __shared__ int s_fgc[Bn], s_lab[Bn];
    __shared__ int s_nb[256];
    int t = threadIdx.x;
    if (t < Bn) { s_fgc[t] = g_fgc[t]; s_lab[t] = labels[t]; }
    __syncthreads();
    int start = 0, cnt = 0, nb = 0;
    if (t < Cc) {
        if (t < Cc-1) {
            #pragma unroll
            for (int i = 0; i < Bn; i++) {
                if (s_lab[i] < t) start += s_fgc[i];
                if (s_lab[i] == t) cnt += s_fgc[i];
            }
        } else {
            int tf = 0;
            #pragma unroll
            for (int i = 0; i < Bn; i++) tf += s_fgc[i];
            start = tf; cnt = Nn - tf;
        }
        nb = (cnt + 511)/512;
    }
    s_nb[t] = nb;
    __syncthreads();
    for (int off = 1; off < 256; off <<= 1) {
        int v = (t >= off) ? s_nb[t-off] : 0;
        __syncthreads();
        s_nb[t] += v;
        __syncthreads();
    }
    int fb = s_nb[t] - nb;
    if (t < Cc) {
        g_cstart[t] = start; g_ccnt[t] = cnt; g_cfb[t] = fb;
        for (int j = 0; j < nb; j++) {
            g_plan_cls[fb+j] = t;
            g_plan_row[fb+j] = start + j*512;
            int e = start + j*512 + 512;
            g_plan_end[fb+j] = (e < start+cnt) ? e : (start+cnt);
        }
    }
    if (t == 255) g_nplan = s_nb[255];
}

// ---------------- sinkhorn phase kernels ----------------
__global__ __launch_bounds__(512) void sh_lmax_part() {
    int b = blockIdx.x;
    if (b >= g_nplan) return;
    int t = threadIdx.x, lane = t & 31, wid = t >> 5;
    __shared__ float wred[16];
    int r = g_plan_row[b] + t;
    float m = -INFINITY;
    if (r < g_plan_end[b]) {
        const float* p = g_Lc + (size_t)r*Kp;
        #pragma unroll
        for (int k = 0; k < Kp; k++) m = fmaxf(m, p[k]);
    }
    #pragma unroll
    for (int o = 16; o > 0; o >>= 1) m = fmaxf(m, __shfl_xor_sync(0xffffffffu, m, o));
    if (lane == 0) wred[wid] = m;
    __syncthreads();
    if (wid == 0) {
        float v = (lane < 16) ? wred[lane] : -INFINITY;
        #pragma unroll
        for (int o = 8; o > 0; o >>= 1) v = fmaxf(v, __shfl_xor_sync(0xffffffffu, v, o));
        if (lane == 0) g_bmax[b] = v;
    }
}

__global__ __launch_bounds__(32) void sh_lmax_red() {
    int c = blockIdx.x;
    int cnt = g_ccnt[c];
    if (cnt == 0 || threadIdx.x != 0) return;
    int fb = g_cfb[c], nb = (cnt + 511)/512;
    float m = -INFINITY;
    for (int j = 0; j < nb; j++) m = fmaxf(m, g_bmax[fb+j]);
    g_lmax[c] = m;
    g_ncinv[c] = 1.0f/fmaxf((float)cnt, 1.0f);
}

__global__ __launch_bounds__(512) void sh_exp_part() {
    int b = blockIdx.x;
    if (b >= g_nplan) return;
    int t = threadIdx.x, lane = t & 31, wid = t >> 5;
    __shared__ float wred[16][Kp];
    int c = g_plan_cls[b];
    float lmax = g_lmax[c];
    int r = g_plan_row[b] + t;
    float v[Kp] = {0,0,0,0,0};
    if (r < g_plan_end[b]) {
        const float* p = g_Lc + (size_t)r*Kp;
        float* q = g_Qc + (size_t)r*Kp;
        #pragma unroll
        for (int k = 0; k < Kp; k++) {
            float e = expf((p[k]-lmax)/0.05f);
            q[k] = e; v[k] = e;
        }
    }
    #pragma unroll
    for (int j = 0; j < Kp; j++)
        #pragma unroll
        for (int o = 16; o > 0; o >>= 1) v[j] += __shfl_xor_sync(0xffffffffu, v[j], o);
    if (lane == 0)
        #pragma unroll
        for (int j = 0; j < Kp; j++) wred[wid][j] = v[j];
    __syncthreads();
    if (wid == 0) {
        float w[Kp];
        #pragma unroll
        for (int j = 0; j < Kp; j++) w[j] = (lane < 16) ? wred[lane][j] : 0.f;
        #pragma unroll
        for (int j = 0; j < Kp; j++)
            #pragma unroll
            for (int o = 8; o > 0; o >>= 1) w[j] += __shfl_xor_sync(0xffffffffu, w[j], o);
        if (lane == 0)
            #pragma unroll
            for (int j = 0; j < Kp; j++) g_bcs[b*Kp + j] = w[j];
    }
}

__global__ __launch_bounds__(32) void sh_exp_red() {
    int c = blockIdx.x;
    int cnt = g_ccnt[c];
    if (cnt == 0 || threadIdx.x != 0) return;
    int fb = g_cfb[c], nb = (cnt + 511)/512;
    float cs[Kp] = {0,0,0,0,0};
    for (int j = 0; j < nb; j++)
        #pragma unroll
        for (int k = 0; k < Kp; k++) cs[k] += g_bcs[(fb+j)*Kp + k];
    float Ttot = fmaxf(cs[0]+cs[1]+cs[2]+cs[3]+cs[4], 1e-12f);
    #pragma unroll
    for (int k = 0; k < Kp; k++) {
        float mk = fmaxf(cs[k]/Ttot, 1e-12f);
        g_a[c*Kp + k] = 1.0f/(Ttot*mk*5.0f);
    }
}

template<bool LAST>
__global__ __launch_bounds__(512) void sh_it_part(float* __restrict__ out_part) {
    int b = blockIdx.x;
    if (b >= g_nplan) return;
    int t = threadIdx.x, lane = t & 31, wid = t >> 5;
    __shared__ float wred[16][Kp];
    int c = g_plan_cls[b];
    float a[Kp];
    #pragma unroll
    for (int k = 0; k < Kp; k++) a[k] = g_a[c*Kp + k];
    float ncinv = g_ncinv[c];
    int r = g_plan_row[b] + t;
    float v[Kp] = {0,0,0,0,0};
    if (r < g_plan_end[b]) {
        float* q = g_Qc + (size_t)r*Kp;
        float w[Kp]; float rs = 0.f;
        #pragma unroll
        for (int k = 0; k < Kp; k++) { w[k] = q[k]*a[k]; rs += w[k]; }
        float rinv = 1.0f/fmaxf(rs, 1e-12f);
        if (!LAST) {
            #pragma unroll
            for (int k = 0; k < Kp; k++) {
                float vv = w[k]*rinv*ncinv;
                q[k] = vv; v[k] = vv;
            }
        } else {
            int bi = 0; float best = -1.f;
            #pragma unroll
            for (int k = 0; k < Kp; k++) {
                float vv = w[k]*rinv;
                q[k] = vv;
                if (vv > best) { best = vv; bi = k; }
            }
            out_part[g_rows[r]] = (float)(bi + c*Kp);
        }
    }
    if (!LAST) {
        #pragma unroll
        for (int j = 0; j < Kp; j++)
            #pragma unroll
            for (int o = 16; o > 0; o >>= 1) v[j] += __shfl_xor_sync(0xffffffffu, v[j], o);
        if (lane == 0)
            #pragma unroll
            for (int j = 0; j < Kp; j++) wred[wid][j] = v[j];
        __syncthreads();
        if (wid == 0) {
            float w[Kp];
            #pragma unroll
            for (int j = 0; j < Kp; j++) w[j] = (lane < 16) ? wred[lane][j] : 0.f;
            #pragma unroll
            for (int j = 0; j < Kp; j++)
                #pragma unroll
                for (int o = 8; o > 0; o >>= 1) w[j] += __shfl_xor_sync(0xffffffffu, w[j], o);
            if (lane == 0)
                #pragma unroll
                for (int j = 0; j < Kp; j++) g_bcs[b*Kp + j] = w[j];
        }
    }
}

__global__ __launch_bounds__(32) void sh_it_red() {
    int c = blockIdx.x;
    int cnt = g_ccnt[c];
    if (cnt == 0 || threadIdx.x != 0) return;
    int fb = g_cfb[c], nb = (cnt + 511)/512;
    float cs[Kp] = {0,0,0,0,0};
    for (int j = 0; j < nb; j++)
        #pragma unroll
        for (int k = 0; k < Kp; k++) cs[k] += g_bcs[(fb+j)*Kp + k];
    #pragma unroll
    for (int k = 0; k < Kp; k++)
        g_a[c*Kp + k] = 1.0f/(fmaxf(cs[k], 1e-12f)*5.0f);
}

// ---------------- P_cand partials (PS=8 splits) ----------------
__global__ __launch_bounds__(128) void pcand_part(const float* __restrict__ patches) {
    int b = blockIdx.x, dc = blockIdx.y, ps = blockIdx.z, t = threadIdx.x;
    float accF[Kp] = {0,0,0,0,0};
    float accB[Kp] = {0,0,0,0,0};
    int n0 = b*NP + ps*162;
    const float* base = patches + (size_t)dc*128 + t;
    #pragma unroll 6
    for (int p = 0; p < 162; p++) {
        int n = n0 + p;
        float v = base[(size_t)n*DIM] * g_invn[n];
        int lab = g_labels_flat[n];
        const float* q = g_Qc + (size_t)g_pos[n]*Kp;
        if (lab == Cc-1) {
            #pragma unroll
            for (int k = 0; k < Kp; k++) accB[k] += q[k]*v;
        } else {
            #pragma unroll
            for (int k = 0; k < Kp; k++) accF[k] += q[k]*v;
        }
    }
    int d = dc*128 + t;
    size_t baseF = ((((size_t)b*PS + ps)*2 + 0)*Kp)*DIM + d;
    size_t baseB = ((((size_t)b*PS + ps)*2 + 1)*Kp)*DIM + d;
    #pragma unroll
    for (int k = 0; k < Kp; k++) {
        g_Ppart[baseF + (size_t)k*DIM] = accF[k];
        g_Ppart[baseB + (size_t)k*DIM] = accB[k];
    }
}

// ---------------- P_new ----------------
__global__ __launch_bounds__(256) void pnew_kernel(const float* __restrict__ proto,
                                                   const int* __restrict__ labels,
                                                   float* __restrict__ out) {
    __shared__ int s_lab[Bn], s_fg[Bn];
    int ck = blockIdx.x, t = threadIdx.x;
    int c = ck/Kp, k = ck - c*Kp;
    if (t < Bn) { s_lab[t] = labels[t]; s_fg[t] = g_fgc[t]; }
    __syncthreads();
    bool isbg = (c == Cc-1);
    bool present;
    if (isbg) {
        int tf = 0;
        #pragma unroll
        for (int b = 0; b < Bn; b++) tf += s_fg[b];
        present = (Nn - tf) > 0;
    } else {
        present = false;
        #pragma unroll
        for (int b = 0; b < Bn; b++)
            if (s_lab[b] == c && s_fg[b] > 0) present = true;
    }
    for (int d = t; d < DIM; d += 256) {
        size_t idx = (size_t)ck*DIM + d;
        float p = proto[idx];
        float r = p;
        if (present) {
            float s = 0.f;
            if (isbg) {
                #pragma unroll
                for (int b = 0; b < Bn; b++)
                    #pragma unroll
                    for (int ps = 0; ps < PS; ps++)
                        s += g_Ppart[((((size_t)b*PS + ps)*2 + 1)*Kp + k)*DIM + d];
            } else {
                for (int b = 0; b < Bn; b++) {
                    if (s_lab[b] == c) {
                        #pragma unroll
                        for (int ps = 0; ps < PS; ps++)
                            s += g_Ppart[((((size_t)b*PS + ps)*2 + 0)*Kp + k)*DIM + d];
                    }
                }
            }
            r = 0.999f*p + 0.001f*s;
        }
        out[idx] = r;
    }
}

// ---------------- launch ----------------
extern "C" void kernel_launch(void* const* d_in, const int* in_sizes, int n_in,
                              void* d_out, int out_size) {
    const float* patch  = (const float*)d_in[0];
    const float* proto  = (const float*)d_in[1];
    const float* sa     = (const float*)d_in[2];
    const float* wf     = (const float*)d_in[3];
    const float* bf     = (const float*)d_in[4];
    const float* wp     = (const float*)d_in[5];
    const float* bp     = (const float*)d_in[6];
    const int*   labels = (const int*)d_in[7];
    float* out  = (float*)d_out;
    float* Lout = out + OFF_L;
    float* img  = out + OFF_IMG;

    const int NH = Nn/2;
    norm_kernel<<<(NH*32)/256, 256>>>(patch, 0);                  // 0
    norm_kernel<<<(NH*32)/256, 256>>>(patch, NH);                 // 1
    feat_gemm<<<Nn/96, 256>>>(patch, wf, bf);                     // 2
    proto_gemm<<<(CK+95)/96, 256>>>(proto, wp, bp);               // 3  <- capture slot
    l_gemm<<<dim3(Nn/96, (CK+63)/64), 256>>>(Lout);               // 4
    imgmax_part<<<dim3(Bn, 16), 1024>>>(Lout);                    // 5
    imgmax_reduce<<<Bn, 1024>>>(img, sa, out + OFF_CLASS);        // 6
    pseudo_kernel<<<Bn, 512>>>(Lout, labels, out + OFF_PSEUDO);   // 7
    compact_kernel<<<Bn, 512>>>(labels, Lout);                    // 8
    plan_kernel<<<1, 256>>>(labels);                              // 9
    sh_lmax_part<<<NBLK, 512>>>();                                // 10
    sh_lmax_red<<<Cc, 32>>>();                                    // 11
    sh_exp_part<<<NBLK, 512>>>();                                 // 12
    sh_exp_red<<<Cc, 32>>>();                                     // 13
    sh_it_part<false><<<NBLK, 512>>>(out + OFF_PART);             // 14
    sh_it_red<<<Cc, 32>>>();                                      // 15
    sh_it_part<false><<<NBLK, 512>>>(out + OFF_PART);             // 16
    sh_it_red<<<Cc, 32>>>();                                      // 17
    sh_it_part<true><<<NBLK, 512>>>(out + OFF_PART);              // 18
    pcand_part<<<dim3(Bn, 6, PS), 128>>>(patch);                  // 19
    pnew_kernel<<<CK, 256>>>(proto, labels, out + OFF_PNEW);      // 20
}

// round 16
// speedup vs baseline: 1.2643x; 1.0188x over previous
#include <cuda_runtime.h>
#include <math.h>

// ---------------- problem constants ----------------
#define Bn   16
#define NP   1296
#define DIM  768
#define Cc   201
#define Kp   5
#define DA   64
#define Nn   (Bn*NP)          // 20736
#define CK   (Cc*Kp)          // 1005

// output layout
#define OFF_CLASS  ((size_t)0)
#define LEN_CLASS  ((size_t)Bn*(Cc-1))
#define OFF_L      (OFF_CLASS + LEN_CLASS)
#define LEN_L      ((size_t)Nn*CK)
#define OFF_IMG    (OFF_L + LEN_L)
#define LEN_IMG    ((size_t)Bn*CK)
#define OFF_PART   (OFF_IMG + LEN_IMG)
#define LEN_PART   ((size_t)Nn)
#define OFF_PSEUDO (OFF_PART + LEN_PART)
#define LEN_PSEUDO ((size_t)Nn)
#define OFF_PNEW   (OFF_PSEUDO + LEN_PSEUDO)

#define FMA2(d,a,b,c) asm("fma.rn.f32x2 %0, %1, %2, %3;" : "=l"(d) : "l"(a), "l"(b), "l"(c))
#define PACK2(d,lo,hi) asm("mov.b64 %0, {%1, %2};" : "=l"(d) : "r"(__float_as_uint(lo)), "r"(__float_as_uint(hi)))

#define NBLK 64
#define PS   8     // pcand patch-splits per image

// ---------------- scratch ----------------
__device__ float g_proto_ad[CK*DA];
__device__ float g_feat_ad[(size_t)Nn*DA];
__device__ float g_invn[Nn];
__device__ int   g_labels_flat[Nn];
__device__ int   g_fgc[Bn];
__device__ int   g_rows[Nn];
__device__ int   g_pos[Nn];
__device__ float g_Lc[(size_t)Nn*Kp];
__device__ float g_Qc[(size_t)Nn*Kp];
__device__ float g_imgpart[(size_t)Bn*16*CK];
__device__ float g_Ppart[(size_t)Bn*PS*2*Kp*DIM];
// sinkhorn plan + partials
__device__ int   g_plan_cls[NBLK];
__device__ int   g_plan_row[NBLK];
__device__ int   g_plan_end[NBLK];
__device__ int   g_nplan;
__device__ int   g_cstart[256], g_ccnt[256], g_cfb[256];
__device__ float g_bmax[NBLK];
__device__ float g_bcs[NBLK*Kp];
__device__ float g_lmax[256];
__device__ float g_a[256*Kp];
__device__ float g_ncinv[256];

// ---------------- inv L2 norm of each patch (half range per launch) ----------------
__global__ __launch_bounds__(256) void norm_kernel(const float* __restrict__ patches, int base) {
    int w = base + ((blockIdx.x*256 + threadIdx.x) >> 5);
    int lane = threadIdx.x & 31;
    if (w >= Nn) return;
    const float4* p = (const float4*)(patches + (size_t)w*DIM);
    float s = 0.f;
    #pragma unroll
    for (int j = 0; j < 6; j++) {
        float4 v = p[lane + 32*j];
        s += v.x*v.x + v.y*v.y + v.z*v.z + v.w*v.w;
    }
    #pragma unroll
    for (int o = 16; o > 0; o >>= 1) s += __shfl_xor_sync(0xffffffffu, s, o);
    if (lane == 0) g_invn[w] = 1.0f/fmaxf(sqrtf(s), 1e-12f);
}

// ---------------- proto_ad per-row (R14 config: 1005 blocks x 64 thr) ----------------
__global__ __launch_bounds__(64) void proto_kernel(const float* __restrict__ proto,
                                                   const float* __restrict__ wp,
                                                   const float* __restrict__ bp) {
    __shared__ float4 rowv[DIM/4];
    __shared__ float red[64];
    int r = blockIdx.x;
    int t = threadIdx.x;
    const float4* src = (const float4*)(proto + (size_t)r*DIM);
    #pragma unroll
    for (int j = 0; j < 3; j++) rowv[t + 64*j] = src[t + 64*j];
    __syncthreads();
    float s0 = bp[t], s1 = 0.f, s2 = 0.f, s3 = 0.f;
    #pragma unroll 4
    for (int d4 = 0; d4 < DIM/4; d4++) {
        float4 rv = rowv[d4];
        int d = d4*4;
        s0 += rv.x*wp[(size_t)d*DA + t];
        s1 += rv.y*wp[(size_t)(d+1)*DA + t];
        s2 += rv.z*wp[(size_t)(d+2)*DA + t];
        s3 += rv.w*wp[(size_t)(d+3)*DA + t];
    }
    float v = 1.f/(1.f + expf(-((s0+s1)+(s2+s3))));
    red[t] = v*v;
    __syncthreads();
    for (int off = 32; off > 0; off >>= 1) {
        if (t < off) red[t] += red[t+off];
        __syncthreads();
    }
    float denom = fmaxf(sqrtf(red[0]), 1e-12f);
    g_proto_ad[(size_t)r*DA + t] = v/denom;
}

// ---------------- feat_ad (96x64, measured config) ----------------
__global__ __launch_bounds__(256) void feat_gemm(const float* __restrict__ A,
                                                 const float* __restrict__ W,
                                                 const float* __restrict__ bias) {
    __shared__ __align__(16) unsigned long long As2[48*64];
    __shared__ float Bs[64][68];
    float* As2f = (float*)As2;
    int m0 = blockIdx.x*96;
    int t = threadIdx.x;
    int tx = t & 15, ty = t >> 4;
    unsigned long long acc2[3][4];
    #pragma unroll
    for (int i = 0; i < 3; i++)
        #pragma unroll
        for (int j = 0; j < 4; j++) acc2[i][j] = 0ull;

    for (int kc = 0; kc < DIM; kc += 64) {
        __syncthreads();
        #pragma unroll
        for (int i = 0; i < 24; i++) {
            int e = i*256 + t;
            int m = e >> 6, kk = e & 63;
            float v = A[(size_t)(m0+m)*DIM + kc + kk];
            As2f[(m >> 1)*128 + kk*2 + (m & 1)] = v;
        }
        #pragma unroll
        for (int i = 0; i < 16; i++) {
            int e = i*256 + t;
            int kk = e >> 6, c = e & 63;
            Bs[kk][c] = W[(size_t)(kc+kk)*DA + c];
        }
        __syncthreads();
        #pragma unroll
        for (int k4 = 0; k4 < 16; k4++) {
            int kk = k4*4;
            unsigned long long b2[4][4];
            #pragma unroll
            for (int jk = 0; jk < 4; jk++) {
                float4 bv = *(const float4*)&Bs[kk+jk][tx*4];
                PACK2(b2[jk][0], bv.x, bv.x);
                PACK2(b2[jk][1], bv.y, bv.y);
                PACK2(b2[jk][2], bv.z, bv.z);
                PACK2(b2[jk][3], bv.w, bv.w);
            }
            #pragma unroll
            for (int mp = 0; mp < 3; mp++) {
                const unsigned long long* arow = &As2[(ty*3+mp)*64 + kk];
                ulonglong2 a01 = *(const ulonglong2*)(arow);
                ulonglong2 a23 = *(const ulonglong2*)(arow + 2);
                #pragma unroll
                for (int j = 0; j < 4; j++) {
                    FMA2(acc2[mp][j], a01.x, b2[0][j], acc2[mp][j]);
                    FMA2(acc2[mp][j], a01.y, b2[1][j], acc2[mp][j]);
                    FMA2(acc2[mp][j], a23.x, b2[2][j], acc2[mp][j]);
                    FMA2(acc2[mp][j], a23.y, b2[3][j], acc2[mp][j]);
                }
            }
        }
    }
    float4 bv = *(const float4*)&bias[tx*4];
    float bb[4] = {bv.x, bv.y, bv.z, bv.w};
    #pragma unroll
    for (int mp = 0; mp < 3; mp++) {
        float4 lo4, hi4;
        float* lop = (float*)&lo4; float* hip = (float*)&hi4;
        #pragma unroll
        for (int j = 0; j < 4; j++) {
            float2 f = *(float2*)&acc2[mp][j];
            lop[j] = 1.f/(1.f + expf(-(f.x + bb[j])));
            hip[j] = 1.f/(1.f + expf(-(f.y + bb[j])));
        }
        int m = m0 + ty*6 + mp*2;
        *(float4*)&g_feat_ad[(size_t)m*DA + tx*4]     = lo4;
        *(float4*)&g_feat_ad[(size_t)(m+1)*DA + tx*4] = hi4;
    }
}

// ---------------- L = feat_ad @ proto_ad^T  (96x64, measured config) ----------------
__global__ __launch_bounds__(256) void l_gemm(float* __restrict__ Lout) {
    __shared__ __align__(16) unsigned long long As2[48*64];
    __shared__ float Bs[64][68];
    float* As2f = (float*)As2;
    int m0 = blockIdx.x*96, n0 = blockIdx.y*64;
    int t = threadIdx.x, tx = t & 15, ty = t >> 4;
    #pragma unroll
    for (int i = 0; i < 24; i++) {
        int e = i*256 + t;
        int m = e >> 6, kk = e & 63;
        float v = g_feat_ad[(size_t)(m0+m)*DA + kk];
        As2f[(m >> 1)*128 + kk*2 + (m & 1)] = v;
    }
    #pragma unroll
    for (int i = 0; i < 16; i++) {
        int e = i*256 + t;
        int n = e >> 6, kk = e & 63;
        Bs[kk][n] = (n0+n < CK) ? g_proto_ad[(size_t)(n0+n)*DA + kk] : 0.f;
    }
    __syncthreads();
    unsigned long long acc2[3][4];
    #pragma unroll
    for (int i = 0; i < 3; i++)
        #pragma unroll
        for (int j = 0; j < 4; j++) acc2[i][j] = 0ull;
    #pragma unroll
    for (int k4 = 0; k4 < 16; k4++) {
        int kk = k4*4;
        unsigned long long b2[4][4];
        #pragma unroll
        for (int jk = 0; jk < 4; jk++) {
            float4 bv = *(const float4*)&Bs[kk+jk][tx*4];
            PACK2(b2[jk][0], bv.x, bv.x);
            PACK2(b2[jk][1], bv.y, bv.y);
            PACK2(b2[jk][2], bv.z, bv.z);
            PACK2(b2[jk][3], bv.w, bv.w);
        }
        #pragma unroll
        for (int mp = 0; mp < 3; mp++) {
            const unsigned long long* arow = &As2[(ty*3+mp)*64 + kk];
            ulonglong2 a01 = *(const ulonglong2*)(arow);
            ulonglong2 a23 = *(const ulonglong2*)(arow + 2);
            #pragma unroll
            for (int j = 0; j < 4; j++) {
                FMA2(acc2[mp][j], a01.x, b2[0][j], acc2[mp][j]);
                FMA2(acc2[mp][j], a01.y, b2[1][j], acc2[mp][j]);
                FMA2(acc2[mp][j], a23.x, b2[2][j], acc2[mp][j]);
                FMA2(acc2[mp][j], a23.y, b2[3][j], acc2[mp][j]);
            }
        }
    }
    #pragma unroll
    for (int mp = 0; mp < 3; mp++) {
        size_t m = (size_t)(m0 + ty*6 + mp*2);
        #pragma unroll
        for (int j = 0; j < 4; j++) {
            int n = n0 + tx*4 + j;
            float2 f = *(float2*)&acc2[mp][j];
            if (n < CK) {
                Lout[m*CK + n]     = f.x;
                Lout[(m+1)*CK + n] = f.y;
            }
        }
    }
}

// ---------------- image_logits stage 1 (3 independent max chains) ----------------
__global__ __launch_bounds__(1024) void imgmax_part(const float* __restrict__ L) {
    int b = blockIdx.x;
    int j = blockIdx.y;
    int ck = threadIdx.x;
    if (ck >= CK) return;
    const float* base = L + ((size_t)b*NP + (size_t)j*81)*CK + ck;
    float m0 = 0.f, m1 = 0.f, m2 = 0.f;
    #pragma unroll 3
    for (int n = 0; n < 81; n += 3) {
        m0 = fmaxf(m0, base[(size_t)n*CK]);
        m1 = fmaxf(m1, base[(size_t)(n+1)*CK]);
        m2 = fmaxf(m2, base[(size_t)(n+2)*CK]);
    }
    g_imgpart[((size_t)b*16 + j)*CK + ck] = fmaxf(fmaxf(m0, m1), m2);
}

// ---------------- image_logits stage 2 + class_logits ----------------
__global__ __launch_bounds__(1024) void imgmax_reduce(float* __restrict__ img,
                                                      const float* __restrict__ sa,
                                                      float* __restrict__ cls) {
    __shared__ float s_img[CK];
    int b = blockIdx.x, ck = threadIdx.x;
    if (ck < CK) {
        float m = 0.f;
        #pragma unroll
        for (int j = 0; j < 16; j++)
            m = fmaxf(m, g_imgpart[((size_t)b*16 + j)*CK + ck]);
        img[(size_t)b*CK + ck] = m;
        s_img[ck] = m;
    }
    __syncthreads();
    int c = ck;
    if (c < Cc-1) {
        float s[Kp]; float mx = -INFINITY;
        #pragma unroll
        for (int k = 0; k < Kp; k++) { s[k] = sa[c*Kp + k]; mx = fmaxf(mx, s[k]); }
        float e[Kp]; float tot = 0.f;
        #pragma unroll
        for (int k = 0; k < Kp; k++) { e[k] = expf(s[k]-mx); tot += e[k]; }
        float acc = 0.f;
        #pragma unroll
        for (int k = 0; k < Kp; k++) acc += s_img[c*Kp + k]*(e[k]/tot*(float)Kp);
        cls[(size_t)b*(Cc-1) + c] = acc;
    }
}

// ---------------- pseudo labels + per-image fg counts ----------------
__global__ __launch_bounds__(512) void pseudo_kernel(const float* __restrict__ L,
                                                     const int* __restrict__ labels,
                                                     float* __restrict__ out_pl) {
    __shared__ float fg[NP], bg[NP];
    __shared__ float red[512];
    __shared__ int ired[512];
    int b = blockIdx.x, t = threadIdx.x;
    int lab = labels[b];
    for (int n = t; n < NP; n += 512) {
        const float* p = L + ((size_t)b*NP + n)*CK;
        float f = 0.f, g = 0.f;
        #pragma unroll
        for (int k = 0; k < Kp; k++) { f += p[lab*Kp + k]; g += p[(Cc-1)*Kp + k]; }
        fg[n] = f; bg[n] = g;
    }
    __syncthreads();
    float sf = 0.f, sb = 0.f;
    for (int n = t; n < NP; n += 512) { sf += fabsf(fg[n]); sb += fabsf(bg[n]); }
    red[t] = sf; __syncthreads();
    for (int off = 256; off > 0; off >>= 1) { if (t < off) red[t] += red[t+off]; __syncthreads(); }
    float Sf = fmaxf(red[0], 1e-12f); __syncthreads();
    red[t] = sb; __syncthreads();
    for (int off = 256; off > 0; off >>= 1) { if (t < off) red[t] += red[t+off]; __syncthreads(); }
    float Sb = fmaxf(red[0], 1e-12f); __syncthreads();
    int fgc = 0;
    for (int n = t; n < NP; n += 512) {
        bool m = (fg[n]/Sf) > (bg[n]/Sb);
        int pl = m ? lab : (Cc-1);
        out_pl[(size_t)b*NP + n] = (float)pl;
        g_labels_flat[b*NP + n] = pl;
        fgc += m ? 1 : 0;
    }
    ired[t] = fgc; __syncthreads();
    for (int off = 256; off > 0; off >>= 1) { if (t < off) ired[t] += ired[t+off]; __syncthreads(); }
    if (t == 0) g_fgc[b] = ired[0];
}

// ---------------- compact rows + gather own-class L into g_Lc ----------------
__global__ __launch_bounds__(512) void compact_kernel(const int* __restrict__ labels,
                                                      const float* __restrict__ L) {
    __shared__ int scan[512];
    __shared__ int s_fgc[Bn], s_lab[Bn];
    int b = blockIdx.x, t = threadIdx.x;
    if (t < Bn) { s_fgc[t] = g_fgc[t]; s_lab[t] = labels[t]; }
    __syncthreads();
    int lab = s_lab[b];
    int fg_base = 0, bg_base = 0, total_fg = 0;
    #pragma unroll
    for (int i = 0; i < Bn; i++) {
        total_fg += s_fgc[i];
        if (s_lab[i] < lab || (s_lab[i] == lab && i < b)) fg_base += s_fgc[i];
        if (i < b) bg_base += NP - s_fgc[i];
    }
    int c0 = t*3;
    int m[3]; int cnt = 0;
    #pragma unroll
    for (int j = 0; j < 3; j++) {
        int n = c0 + j;
        int f = 0;
        if (n < NP) f = (g_labels_flat[b*NP + n] != Cc-1) ? 1 : 0;
        m[j] = f; cnt += f;
    }
    scan[t] = cnt;
    __syncthreads();
    for (int off = 1; off < 512; off <<= 1) {
        int v = (t >= off) ? scan[t-off] : 0;
        __syncthreads();
        scan[t] += v;
        __syncthreads();
    }
    int fgr = scan[t] - cnt;
    #pragma unroll
    for (int j = 0; j < 3; j++) {
        int n = c0 + j;
        if (n < NP) {
            int gn = b*NP + n;
            int idx, cc;
            if (m[j]) { idx = fg_base + fgr; fgr++; cc = lab; }
            else      { idx = total_fg + bg_base + (n - fgr); cc = Cc-1; }
            g_rows[idx] = gn;
            g_pos[gn]   = idx;
            const float* ps = L + (size_t)gn*CK + cc*Kp;
            float* lc = g_Lc + (size_t)idx*Kp;
            #pragma unroll
            for (int k = 0; k < Kp; k++) lc[k] = ps[k];
        }
    }
}

// ---------------- sinkhorn plan ----------------
__global__ __launch_bounds__(256) void plan_kernel(const int* __restrict__ labels) {
    __shared__ int s_fgc[Bn], s_lab[Bn];
    __shared__ int s_nb[256];
    int t = threadIdx.x;
    if (t < Bn) { s_fgc[t] = g_fgc[t]; s_lab[t] = labels[t]; }
    __syncthreads();
    int start = 0, cnt = 0, nb = 0;
    if (t < Cc) {
        if (t < Cc-1) {
            #pragma unroll
            for (int i = 0; i < Bn; i++) {
                if (s_lab[i] < t) start += s_fgc[i];
                if (s_lab[i] == t) cnt += s_fgc[i];
            }
        } else {
            int tf = 0;
            #pragma unroll
            for (int i = 0; i < Bn; i++) tf += s_fgc[i];
            start = tf; cnt = Nn - tf;
        }
        nb = (cnt + 511)/512;
    }
    s_nb[t] = nb;
    __syncthreads();
    for (int off = 1; off < 256; off <<= 1) {
        int v = (t >= off) ? s_nb[t-off] : 0;
        __syncthreads();
        s_nb[t] += v;
        __syncthreads();
    }
    int fb = s_nb[t] - nb;
    if (t < Cc) {
        g_cstart[t] = start; g_ccnt[t] = cnt; g_cfb[t] = fb;
        for (int j = 0; j < nb; j++) {
            g_plan_cls[fb+j] = t;
            g_plan_row[fb+j] = start + j*512;
            int e = start + j*512 + 512;
            g_plan_end[fb+j] = (e < start+cnt) ? e : (start+cnt);
        }
    }
    if (t == 255) g_nplan = s_nb[255];
}

// ---------------- sinkhorn phase kernels ----------------
__global__ __launch_bounds__(512) void sh_lmax_part() {
    int b = blockIdx.x;
    if (b >= g_nplan) return;
    int t = threadIdx.x, lane = t & 31, wid = t >> 5;
    __shared__ float wred[16];
    int r = g_plan_row[b] + t;
    float m = -INFINITY;
    if (r < g_plan_end[b]) {
        const float* p = g_Lc + (size_t)r*Kp;
        #pragma unroll
        for (int k = 0; k < Kp; k++) m = fmaxf(m, p[k]);
    }
    #pragma unroll
    for (int o = 16; o > 0; o >>= 1) m = fmaxf(m, __shfl_xor_sync(0xffffffffu, m, o));
    if (lane == 0) wred[wid] = m;
    __syncthreads();
    if (wid == 0) {
        float v = (lane < 16) ? wred[lane] : -INFINITY;
        #pragma unroll
        for (int o = 8; o > 0; o >>= 1) v = fmaxf(v, __shfl_xor_sync(0xffffffffu, v, o));
        if (lane == 0) g_bmax[b] = v;
    }
}

__global__ __launch_bounds__(32) void sh_lmax_red() {
    int c = blockIdx.x;
    int cnt = g_ccnt[c];
    if (cnt == 0 || threadIdx.x != 0) return;
    int fb = g_cfb[c], nb = (cnt + 511)/512;
    float m = -INFINITY;
    for (int j = 0; j < nb; j++) m = fmaxf(m, g_bmax[fb+j]);
    g_lmax[c] = m;
    g_ncinv[c] = 1.0f/fmaxf((float)cnt, 1.0f);
}

__global__ __launch_bounds__(512) void sh_exp_part() {
    int b = blockIdx.x;
    if (b >= g_nplan) return;
    int t = threadIdx.x, lane = t & 31, wid = t >> 5;
    __shared__ float wred[16][Kp];
    int c = g_plan_cls[b];
    float lmax = g_lmax[c];
    int r = g_plan_row[b] + t;
    float v[Kp] = {0,0,0,0,0};
    if (r < g_plan_end[b]) {
        const float* p = g_Lc + (size_t)r*Kp;
        float* q = g_Qc + (size_t)r*Kp;
        #pragma unroll
        for (int k = 0; k < Kp; k++) {
            float e = expf((p[k]-lmax)/0.05f);
            q[k] = e; v[k] = e;
        }
    }
    #pragma unroll
    for (int j = 0; j < Kp; j++)
        #pragma unroll
        for (int o = 16; o > 0; o >>= 1) v[j] += __shfl_xor_sync(0xffffffffu, v[j], o);
    if (lane == 0)
        #pragma unroll
        for (int j = 0; j < Kp; j++) wred[wid][j] = v[j];
    __syncthreads();
    if (wid == 0) {
        float w[Kp];
        #pragma unroll
        for (int j = 0; j < Kp; j++) w[j] = (lane < 16) ? wred[lane][j] : 0.f;
        #pragma unroll
        for (int j = 0; j < Kp; j++)
            #pragma unroll
            for (int o = 8; o > 0; o >>= 1) w[j] += __shfl_xor_sync(0xffffffffu, w[j], o);
        if (lane == 0)
            #pragma unroll
            for (int j = 0; j < Kp; j++) g_bcs[b*Kp + j] = w[j];
    }
}

__global__ __launch_bounds__(32) void sh_exp_red() {
    int c = blockIdx.x;
    int cnt = g_ccnt[c];
    if (cnt == 0 || threadIdx.x != 0) return;
    int fb = g_cfb[c], nb = (cnt + 511)/512;
    float cs[Kp] = {0,0,0,0,0};
    for (int j = 0; j < nb; j++)
        #pragma unroll
        for (int k = 0; k < Kp; k++) cs[k] += g_bcs[(fb+j)*Kp + k];
    float Ttot = fmaxf(cs[0]+cs[1]+cs[2]+cs[3]+cs[4], 1e-12f);
    #pragma unroll
    for (int k = 0; k < Kp; k++) {
        float mk = fmaxf(cs[k]/Ttot, 1e-12f);
        g_a[c*Kp + k] = 1.0f/(Ttot*mk*5.0f);
    }
}

template<bool LAST>
__global__ __launch_bounds__(512) void sh_it_part(float* __restrict__ out_part) {
    int b = blockIdx.x;
    if (b >= g_nplan) return;
    int t = threadIdx.x, lane = t & 31, wid = t >> 5;
    __shared__ float wred[16][Kp];
    int c = g_plan_cls[b];
    float a[Kp];
    #pragma unroll
    for (int k = 0; k < Kp; k++) a[k] = g_a[c*Kp + k];
    float ncinv = g_ncinv[c];
    int r = g_plan_row[b] + t;
    float v[Kp] = {0,0,0,0,0};
    if (r < g_plan_end[b]) {
        float* q = g_Qc + (size_t)r*Kp;
        float w[Kp]; float rs = 0.f;
        #pragma unroll
        for (int k = 0; k < Kp; k++) { w[k] = q[k]*a[k]; rs += w[k]; }
        float rinv = 1.0f/fmaxf(rs, 1e-12f);
        if (!LAST) {
            #pragma unroll
            for (int k = 0; k < Kp; k++) {
                float vv = w[k]*rinv*ncinv;
                q[k] = vv; v[k] = vv;
            }
        } else {
            int bi = 0; float best = -1.f;
            #pragma unroll
            for (int k = 0; k < Kp; k++) {
                float vv = w[k]*rinv;
                q[k] = vv;
                if (vv > best) { best = vv; bi = k; }
            }
            out_part[g_rows[r]] = (float)(bi + c*Kp);
        }
    }
    if (!LAST) {
        #pragma unroll
        for (int j = 0; j < Kp; j++)
            #pragma unroll
            for (int o = 16; o > 0; o >>= 1) v[j] += __shfl_xor_sync(0xffffffffu, v[j], o);
        if (lane == 0)
            #pragma unroll
            for (int j = 0; j < Kp; j++) wred[wid][j] = v[j];
        __syncthreads();
        if (wid == 0) {
            float w[Kp];
            #pragma unroll
            for (int j = 0; j < Kp; j++) w[j] = (lane < 16) ? wred[lane][j] : 0.f;
            #pragma unroll
            for (int j = 0; j < Kp; j++)
                #pragma unroll
                for (int o = 8; o > 0; o >>= 1) w[j] += __shfl_xor_sync(0xffffffffu, w[j], o);
            if (lane == 0)
                #pragma unroll
                for (int j = 0; j < Kp; j++) g_bcs[b*Kp + j] = w[j];
        }
    }
}

__global__ __launch_bounds__(32) void sh_it_red() {
    int c = blockIdx.x;
    int cnt = g_ccnt[c];
    if (cnt == 0 || threadIdx.x != 0) return;
    int fb = g_cfb[c], nb = (cnt + 511)/512;
    float cs[Kp] = {0,0,0,0,0};
    for (int j = 0; j < nb; j++)
        #pragma unroll
        for (int k = 0; k < Kp; k++) cs[k] += g_bcs[(fb+j)*Kp + k];
    #pragma unroll
    for (int k = 0; k < Kp; k++)
        g_a[c*Kp + k] = 1.0f/(fmaxf(cs[k], 1e-12f)*5.0f);
}

// ---------------- P_cand partials (PS=8 splits) ----------------
__global__ __launch_bounds__(128) void pcand_part(const float* __restrict__ patches) {
    int b = blockIdx.x, dc = blockIdx.y, ps = blockIdx.z, t = threadIdx.x;
    float accF[Kp] = {0,0,0,0,0};
    float accB[Kp] = {0,0,0,0,0};
    int n0 = b*NP + ps*162;
    const float* base = patches + (size_t)dc*128 + t;
    #pragma unroll 6
    for (int p = 0; p < 162; p++) {
        int n = n0 + p;
        float v = base[(size_t)n*DIM] * g_invn[n];
        int lab = g_labels_flat[n];
        const float* q = g_Qc + (size_t)g_pos[n]*Kp;
        if (lab == Cc-1) {
            #pragma unroll
            for (int k = 0; k < Kp; k++) accB[k] += q[k]*v;
        } else {
            #pragma unroll
            for (int k = 0; k < Kp; k++) accF[k] += q[k]*v;
        }
    }
    int d = dc*128 + t;
    size_t baseF = ((((size_t)b*PS + ps)*2 + 0)*Kp)*DIM + d;
    size_t baseB = ((((size_t)b*PS + ps)*2 + 1)*Kp)*DIM + d;
    #pragma unroll
    for (int k = 0; k < Kp; k++) {
        g_Ppart[baseF + (size_t)k*DIM] = accF[k];
        g_Ppart[baseB + (size_t)k*DIM] = accB[k];
    }
}

// ---------------- P_new ----------------
__global__ __launch_bounds__(256) void pnew_kernel(const float* __restrict__ proto,
                                                   const int* __restrict__ labels,
                                                   float* __restrict__ out) {
    __shared__ int s_lab[Bn], s_fg[Bn];
    int ck = blockIdx.x, t = threadIdx.x;
    int c = ck/Kp, k = ck - c*Kp;
    if (t < Bn) { s_lab[t] = labels[t]; s_fg[t] = g_fgc[t]; }
    __syncthreads();
    bool isbg = (c == Cc-1);
    bool present;
    if (isbg) {
        int tf = 0;
        #pragma unroll
        for (int b = 0; b < Bn; b++) tf += s_fg[b];
        present = (Nn - tf) > 0;
    } else {
        present = false;
        #pragma unroll
        for (int b = 0; b < Bn; b++)
            if (s_lab[b] == c && s_fg[b] > 0) present = true;
    }
    for (int d = t; d < DIM; d += 256) {
        size_t idx = (size_t)ck*DIM + d;
        float p = proto[idx];
        float r = p;
        if (present) {
            float s = 0.f;
            if (isbg) {
                #pragma unroll
                for (int b = 0; b < Bn; b++)
                    #pragma unroll
                    for (int ps = 0; ps < PS; ps++)
                        s += g_Ppart[((((size_t)b*PS + ps)*2 + 1)*Kp + k)*DIM + d];
            } else {
                for (int b = 0; b < Bn; b++) {
                    if (s_lab[b] == c) {
                        #pragma unroll
                        for (int ps = 0; ps < PS; ps++)
                            s += g_Ppart[((((size_t)b*PS + ps)*2 + 0)*Kp + k)*DIM + d];
                    }
                }
            }
            r = 0.999f*p + 0.001f*s;
        }
        out[idx] = r;
    }
}

// ---------------- launch ----------------
extern "C" void kernel_launch(void* const* d_in, const int* in_sizes, int n_in,
                              void* d_out, int out_size) {
    const float* patch  = (const float*)d_in[0];
    const float* proto  = (const float*)d_in[1];
    const float* sa     = (const float*)d_in[2];
    const float* wf     = (const float*)d_in[3];
    const float* bf     = (const float*)d_in[4];
    const float* wp     = (const float*)d_in[5];
    const float* bp     = (const float*)d_in[6];
    const int*   labels = (const int*)d_in[7];
    float* out  = (float*)d_out;
    float* Lout = out + OFF_L;
    float* img  = out + OFF_IMG;

    const int NH = Nn/2;
    norm_kernel<<<(NH*32)/256, 256>>>(patch, 0);                  // 0
    norm_kernel<<<(NH*32)/256, 256>>>(patch, NH);                 // 1
    feat_gemm<<<Nn/96, 256>>>(patch, wf, bf);                     // 2
    proto_kernel<<<CK, 64>>>(proto, wp, bp);                      // 3  <- capture slot
    l_gemm<<<dim3(Nn/96, (CK+63)/64), 256>>>(Lout);               // 4
    imgmax_part<<<dim3(Bn, 16), 1024>>>(Lout);                    // 5
    imgmax_reduce<<<Bn, 1024>>>(img, sa, out + OFF_CLASS);        // 6
    pseudo_kernel<<<Bn, 512>>>(Lout, labels, out + OFF_PSEUDO);   // 7
    compact_kernel<<<Bn, 512>>>(labels, Lout);                    // 8
    plan_kernel<<<1, 256>>>(labels);                              // 9
    sh_lmax_part<<<NBLK, 512>>>();                                // 10
    sh_lmax_red<<<Cc, 32>>>();                                    // 11
    sh_exp_part<<<NBLK, 512>>>();                                 // 12
    sh_exp_red<<<Cc, 32>>>();                                     // 13
    sh_it_part<false><<<NBLK, 512>>>(out + OFF_PART);             // 14
    sh_it_red<<<Cc, 32>>>();                                      // 15
    sh_it_part<false><<<NBLK, 512>>>(out + OFF_PART);             // 16
    sh_it_red<<<Cc, 32>>>();                                      // 17
    sh_it_part<true><<<NBLK, 512>>>(out + OFF_PART);              // 18
    pcand_part<<<dim3(Bn, 6, PS), 128>>>(patch);                  // 19
    pnew_kernel<<<CK, 256>>>(proto, labels, out + OFF_PNEW);      // 20
}